// round 1
// baseline (speedup 1.0000x reference)
#include <cuda_runtime.h>
#include <math.h>

#define B_   4
#define S_   1024
#define D_   1024
#define H_   16
#define HD_  64
#define FF_  4096
#define NT   (B_*S_)          // 4096 tokens
#define NEGV (-1e9f)

// ---------------- scratch (__device__ globals; no allocs allowed) ----------
__device__ float g_qkv [NT * 3 * D_];   // 48 MB
__device__ float g_ctx [NT * D_];       // 16 MB
__device__ float g_attn[NT * D_];       // 16 MB
__device__ float g_h   [NT * D_];       // 16 MB
__device__ float g_ffn1[NT * FF_];      // 64 MB
__device__ float g_ffn2[NT * D_];       // 16 MB
__device__ int   g_mask_mode;           // 0=int32, 1=byte, 2=float

// ---------------- mask dtype probe ----------------------------------------
// mask is logically bool[4,16,1024] = 65536 elements. We can safely read
// 65536 BYTES under any candidate layout (smallest is 64 KiB for uint8).
//  - int32 0/1  : byte groups [v,0,0,0]
//  - uint8 0/1  : random nonzero bytes at all offsets
//  - float 0/1.0: 1.0f = 00 00 80 3f -> contains 0x3f bytes
__global__ void detect_mask_kernel(const unsigned char* __restrict__ m) {
    __shared__ int f3f, foff;
    if (threadIdx.x == 0) { f3f = 0; foff = 0; }
    __syncthreads();
    int l3f = 0, loff = 0;
    for (int i = threadIdx.x; i < 65536; i += blockDim.x) {
        unsigned char v = m[i];
        if (v == 0x3f) l3f = 1;
        else if (v && (i & 3)) loff = 1;
    }
    if (l3f)  atomicOr(&f3f, 1);
    if (loff) atomicOr(&foff, 1);
    __syncthreads();
    if (threadIdx.x == 0) g_mask_mode = f3f ? 2 : (foff ? 1 : 0);
}

__device__ __forceinline__ float mask_val(const void* mp, int idx) {
    int mode = g_mask_mode;
    if (mode == 0) return ((const int*)mp)[idx] ? 1.f : 0.f;
    if (mode == 1) return ((const unsigned char*)mp)[idx] ? 1.f : 0.f;
    return ((const float*)mp)[idx];
}

// ---------------- generic SGEMM: C[M,N] = A[M,K] * B[N,K]^T + bias --------
// Both operands K-major (row-major with K contiguous). 128x128 tile,
// BK=16, 256 threads, 8x8 microtile per thread.
template<int RELU>
__global__ void __launch_bounds__(256, 2) sgemm_bt(
    const float* __restrict__ A, const float* __restrict__ Bm,
    const float* __restrict__ bias, float* __restrict__ C,
    int M, int N, int K)
{
    __shared__ float As[16][128];
    __shared__ float Bs[16][128];
    const int tid  = threadIdx.x;
    const int tx   = tid & 15;
    const int ty   = tid >> 4;
    const int row0 = blockIdx.y * 128;
    const int col0 = blockIdx.x * 128;
    const int lr   = tid >> 2;          // 0..63
    const int lc   = (tid & 3) << 2;    // 0,4,8,12

    const float* Ap = A  + (size_t)(row0 + lr) * K + lc;
    const float* Bp = Bm + (size_t)(col0 + lr) * K + lc;

    float acc[8][8];
    #pragma unroll
    for (int i = 0; i < 8; i++)
        #pragma unroll
        for (int j = 0; j < 8; j++) acc[i][j] = 0.f;

    for (int k0 = 0; k0 < K; k0 += 16) {
        float4 a0 = *(const float4*)(Ap + k0);
        float4 a1 = *(const float4*)(Ap + (size_t)64 * K + k0);
        float4 b0 = *(const float4*)(Bp + k0);
        float4 b1 = *(const float4*)(Bp + (size_t)64 * K + k0);
        __syncthreads();   // previous tile's compute done
        As[lc+0][lr]    = a0.x; As[lc+1][lr]    = a0.y; As[lc+2][lr]    = a0.z; As[lc+3][lr]    = a0.w;
        As[lc+0][lr+64] = a1.x; As[lc+1][lr+64] = a1.y; As[lc+2][lr+64] = a1.z; As[lc+3][lr+64] = a1.w;
        Bs[lc+0][lr]    = b0.x; Bs[lc+1][lr]    = b0.y; Bs[lc+2][lr]    = b0.z; Bs[lc+3][lr]    = b0.w;
        Bs[lc+0][lr+64] = b1.x; Bs[lc+1][lr+64] = b1.y; Bs[lc+2][lr+64] = b1.z; Bs[lc+3][lr+64] = b1.w;
        __syncthreads();
        #pragma unroll
        for (int k = 0; k < 16; k++) {
            float4 a4 = *(const float4*)&As[k][ty * 8];
            float4 a5 = *(const float4*)&As[k][ty * 8 + 4];
            float4 b4 = *(const float4*)&Bs[k][tx * 8];
            float4 b5 = *(const float4*)&Bs[k][tx * 8 + 4];
            float ar[8] = {a4.x, a4.y, a4.z, a4.w, a5.x, a5.y, a5.z, a5.w};
            float br[8] = {b4.x, b4.y, b4.z, b4.w, b5.x, b5.y, b5.z, b5.w};
            #pragma unroll
            for (int i = 0; i < 8; i++)
                #pragma unroll
                for (int j = 0; j < 8; j++)
                    acc[i][j] = fmaf(ar[i], br[j], acc[i][j]);
        }
    }

    #pragma unroll
    for (int i = 0; i < 8; i++) {
        int r = row0 + ty * 8 + i;
        #pragma unroll
        for (int j = 0; j < 8; j++) {
            int c = col0 + tx * 8 + j;
            float v = acc[i][j] + bias[c];
            if (RELU) v = fmaxf(v, 0.f);
            C[(size_t)r * N + c] = v;
        }
    }
}

// ---------------- attention (flash-style, 64x64 tiles) --------------------
__device__ __forceinline__ float shfl_max16(float v) {
    #pragma unroll
    for (int o = 8; o; o >>= 1) v = fmaxf(v, __shfl_xor_sync(0xffffffffu, v, o, 16));
    return v;
}
__device__ __forceinline__ float shfl_sum16(float v) {
    #pragma unroll
    for (int o = 8; o; o >>= 1) v += __shfl_xor_sync(0xffffffffu, v, o, 16);
    return v;
}

#define ATTN_PAD 65
#define SMEM_ATTN ((4 * 64 * ATTN_PAD + 64) * (int)sizeof(float))

__global__ void __launch_bounds__(256) attn_kernel(
    const float* __restrict__ qkv, const void* __restrict__ mask,
    float* __restrict__ ctx)
{
    const int it = blockIdx.x;   // i tile (0..15)
    const int h  = blockIdx.y;
    const int b  = blockIdx.z;

    extern __shared__ float sm[];
    float* Qs = sm;
    float* Ks = Qs + 64 * ATTN_PAD;
    float* Vs = Ks + 64 * ATTN_PAD;
    float* Ps = Vs + 64 * ATTN_PAD;
    float* mk = Ps + 64 * ATTN_PAD;

    const int tid = threadIdx.x;
    const int tx  = tid & 15;
    const int ty  = tid >> 4;
    const float scale = 0.125f;  // hd^-0.5

    const int rowbase = b * S_;
    const int qcol = h * HD_;
    const int i0 = it * 64;

    // load Q tile [64 x 64]
    for (int t = tid; t < 64 * 16; t += 256) {
        int r = t >> 4, c4 = (t & 15) << 2;
        float4 v = *(const float4*)(qkv + (size_t)(rowbase + i0 + r) * (3 * D_) + qcol + c4);
        Qs[r * ATTN_PAD + c4 + 0] = v.x;
        Qs[r * ATTN_PAD + c4 + 1] = v.y;
        Qs[r * ATTN_PAD + c4 + 2] = v.z;
        Qs[r * ATTN_PAD + c4 + 3] = v.w;
    }

    float m_run[4], l_run[4], acc[4][4];
    #pragma unroll
    for (int r = 0; r < 4; r++) {
        m_run[r] = -3.0e38f; l_run[r] = 0.f;
        #pragma unroll
        for (int c = 0; c < 4; c++) acc[r][c] = 0.f;
    }

    for (int j0 = 0; j0 < S_; j0 += 64) {
        __syncthreads();  // prev iteration readers done (also covers Qs load)
        for (int t = tid; t < 64 * 16; t += 256) {
            int r = t >> 4, c4 = (t & 15) << 2;
            const float* base = qkv + (size_t)(rowbase + j0 + r) * (3 * D_) + qcol;
            float4 kv = *(const float4*)(base + D_ + c4);
            float4 vv = *(const float4*)(base + 2 * D_ + c4);
            Ks[r * ATTN_PAD + c4 + 0] = kv.x; Ks[r * ATTN_PAD + c4 + 1] = kv.y;
            Ks[r * ATTN_PAD + c4 + 2] = kv.z; Ks[r * ATTN_PAD + c4 + 3] = kv.w;
            Vs[r * ATTN_PAD + c4 + 0] = vv.x; Vs[r * ATTN_PAD + c4 + 1] = vv.y;
            Vs[r * ATTN_PAD + c4 + 2] = vv.z; Vs[r * ATTN_PAD + c4 + 3] = vv.w;
        }
        if (tid < 64) mk[tid] = mask_val(mask, (b * H_ + h) * S_ + j0 + tid);
        __syncthreads();

        // S tile: thread owns rows ty*4.. cols tx*4..
        float s[4][4];
        #pragma unroll
        for (int r = 0; r < 4; r++)
            #pragma unroll
            for (int c = 0; c < 4; c++) s[r][c] = 0.f;
        #pragma unroll 8
        for (int d = 0; d < 64; d++) {
            float qv[4], kv[4];
            #pragma unroll
            for (int r = 0; r < 4; r++) qv[r] = Qs[(ty * 4 + r) * ATTN_PAD + d];
            #pragma unroll
            for (int c = 0; c < 4; c++) kv[c] = Ks[(tx * 4 + c) * ATTN_PAD + d];
            #pragma unroll
            for (int r = 0; r < 4; r++)
                #pragma unroll
                for (int c = 0; c < 4; c++) s[r][c] = fmaf(qv[r], kv[c], s[r][c]);
        }
        float mkv[4];
        #pragma unroll
        for (int c = 0; c < 4; c++) mkv[c] = mk[tx * 4 + c];
        #pragma unroll
        for (int r = 0; r < 4; r++)
            #pragma unroll
            for (int c = 0; c < 4; c++)
                s[r][c] = (mkv[c] > 0.5f) ? s[r][c] * scale : NEGV;

        // online softmax: row max / exp / row sum (reduce across the 16 tx)
        float corr[4];
        #pragma unroll
        for (int r = 0; r < 4; r++) {
            float mt = fmaxf(fmaxf(s[r][0], s[r][1]), fmaxf(s[r][2], s[r][3]));
            mt = shfl_max16(mt);
            float nm = fmaxf(m_run[r], mt);
            corr[r] = __expf(m_run[r] - nm);
            m_run[r] = nm;
        }
        #pragma unroll
        for (int r = 0; r < 4; r++) {
            float rs = 0.f;
            #pragma unroll
            for (int c = 0; c < 4; c++) {
                float p = __expf(s[r][c] - m_run[r]);
                Ps[(ty * 4 + r) * ATTN_PAD + tx * 4 + c] = p;
                rs += p;
            }
            rs = shfl_sum16(rs);
            l_run[r] = l_run[r] * corr[r] + rs;
        }
        __syncthreads();  // Ps visible

        #pragma unroll
        for (int r = 0; r < 4; r++)
            #pragma unroll
            for (int c = 0; c < 4; c++) acc[r][c] *= corr[r];
        #pragma unroll 8
        for (int j = 0; j < 64; j++) {
            float pv[4], vv[4];
            #pragma unroll
            for (int r = 0; r < 4; r++) pv[r] = Ps[(ty * 4 + r) * ATTN_PAD + j];
            #pragma unroll
            for (int c = 0; c < 4; c++) vv[c] = Vs[j * ATTN_PAD + tx * 4 + c];
            #pragma unroll
            for (int r = 0; r < 4; r++)
                #pragma unroll
                for (int c = 0; c < 4; c++) acc[r][c] = fmaf(pv[r], vv[c], acc[r][c]);
        }
    }

    #pragma unroll
    for (int r = 0; r < 4; r++) {
        float inv = 1.f / l_run[r];
        #pragma unroll
        for (int c = 0; c < 4; c++) {
            ctx[(size_t)(rowbase + i0 + ty * 4 + r) * D_ + qcol + tx * 4 + c] = acc[r][c] * inv;
        }
    }
}

// ---------------- residual + LayerNorm ------------------------------------
__global__ void __launch_bounds__(256) ln_residual_kernel(
    const float* __restrict__ a, const float* __restrict__ res,
    const float* __restrict__ gamma, const float* __restrict__ beta,
    float* __restrict__ out)
{
    const int row = blockIdx.x;
    const int tid = threadIdx.x;
    const float* pa = a   + (size_t)row * D_;
    const float* pr = res + (size_t)row * D_;

    float v[4], sum = 0.f, sq = 0.f;
    #pragma unroll
    for (int i = 0; i < 4; i++) {
        int c = tid + i * 256;
        float t = pa[c] + pr[c];
        v[i] = t; sum += t; sq += t * t;
    }
    #pragma unroll
    for (int o = 16; o; o >>= 1) {
        sum += __shfl_xor_sync(0xffffffffu, sum, o);
        sq  += __shfl_xor_sync(0xffffffffu, sq,  o);
    }
    __shared__ float sh1[8], sh2[8];
    __shared__ float smean, srstd;
    if ((tid & 31) == 0) { sh1[tid >> 5] = sum; sh2[tid >> 5] = sq; }
    __syncthreads();
    if (tid == 0) {
        float s = 0.f, s2 = 0.f;
        #pragma unroll
        for (int i = 0; i < 8; i++) { s += sh1[i]; s2 += sh2[i]; }
        float mean = s * (1.f / D_);
        float var  = s2 * (1.f / D_) - mean * mean;
        smean = mean;
        srstd = rsqrtf(var + 1e-12f);
    }
    __syncthreads();
    float mean = smean, rstd = srstd;
    #pragma unroll
    for (int i = 0; i < 4; i++) {
        int c = tid + i * 256;
        out[(size_t)row * D_ + c] = gamma[c] * (v[i] - mean) * rstd + beta[c];
    }
}

// ---------------- launch ---------------------------------------------------
extern "C" void kernel_launch(void* const* d_in, const int* in_sizes, int n_in,
                              void* d_out, int out_size)
{
    const float* x    = (const float*)d_in[0];
    const void*  mask = d_in[1];
    const float* Wqkv = (const float*)d_in[2];
    const float* bqkv = (const float*)d_in[3];
    const float* Wo   = (const float*)d_in[4];
    const float* bo   = (const float*)d_in[5];
    const float* W1   = (const float*)d_in[6];
    const float* b1   = (const float*)d_in[7];
    const float* W2   = (const float*)d_in[8];
    const float* b2   = (const float*)d_in[9];
    const float* g1   = (const float*)d_in[10];
    const float* be1  = (const float*)d_in[11];
    const float* g2   = (const float*)d_in[12];
    const float* be2  = (const float*)d_in[13];
    float* out = (float*)d_out;

    float *qkv, *ctx, *attn, *hbuf, *f1, *f2;
    cudaGetSymbolAddress((void**)&qkv,  g_qkv);
    cudaGetSymbolAddress((void**)&ctx,  g_ctx);
    cudaGetSymbolAddress((void**)&attn, g_attn);
    cudaGetSymbolAddress((void**)&hbuf, g_h);
    cudaGetSymbolAddress((void**)&f1,   g_ffn1);
    cudaGetSymbolAddress((void**)&f2,   g_ffn2);

    cudaFuncSetAttribute(attn_kernel,
                         cudaFuncAttributeMaxDynamicSharedMemorySize, SMEM_ATTN);

    detect_mask_kernel<<<1, 256>>>((const unsigned char*)mask);

    // qkv = x @ Wqkv^T + bqkv : [4096, 3072]
    sgemm_bt<0><<<dim3(3 * D_ / 128, NT / 128), 256>>>(x, Wqkv, bqkv, qkv, NT, 3 * D_, D_);

    // attention -> ctx [4096, 1024]
    attn_kernel<<<dim3(S_ / 64, H_, B_), 256, SMEM_ATTN>>>(qkv, mask, ctx);

    // attn_out = ctx @ Wo^T + bo
    sgemm_bt<0><<<dim3(D_ / 128, NT / 128), 256>>>(ctx, Wo, bo, attn, NT, D_, D_);

    // h = LN1(attn_out + x)
    ln_residual_kernel<<<NT, 256>>>(attn, x, g1, be1, hbuf);

    // ffn1 = relu(h @ W1^T + b1) : [4096, 4096]
    sgemm_bt<1><<<dim3(FF_ / 128, NT / 128), 256>>>(hbuf, W1, b1, f1, NT, FF_, D_);

    // ffn2 = ffn1 @ W2^T + b2 : [4096, 1024]
    sgemm_bt<0><<<dim3(D_ / 128, NT / 128), 256>>>(f1, W2, b2, f2, NT, D_, FF_);

    // out = LN2(ffn2 + h)
    ln_residual_kernel<<<NT, 256>>>(f2, hbuf, g2, be2, out);
}

// round 3
// speedup vs baseline: 1.8309x; 1.8309x over previous
#include <cuda_runtime.h>
#include <cuda_bf16.h>
#include <math.h>
#include <stdint.h>

#define B_   4
#define S_   1024
#define D_   1024
#define H_   16
#define HD_  64
#define FF_  4096
#define NT   (B_*S_)          // 4096 tokens
#define NEGV (-1e9f)

// ---------------- scratch (__device__ globals; no allocs allowed) ----------
__device__ float g_qkv [NT * 3 * D_];
__device__ float g_ctx [NT * D_];
__device__ float g_attn[NT * D_];
__device__ float g_h   [NT * D_];
__device__ float g_ffn1[NT * FF_];
__device__ float g_ffn2[NT * D_];
__device__ int   g_mask_mode;           // 0=int32, 1=byte, 2=float

// bf16 split buffers
__device__ __nv_bfloat16 g_wqkv_h[3*D_*D_], g_wqkv_l[3*D_*D_];
__device__ __nv_bfloat16 g_wo_h  [D_*D_],   g_wo_l  [D_*D_];
__device__ __nv_bfloat16 g_w1_h  [FF_*D_],  g_w1_l  [FF_*D_];
__device__ __nv_bfloat16 g_w2_h  [D_*FF_],  g_w2_l  [D_*FF_];
__device__ __nv_bfloat16 g_act_h [NT*FF_],  g_act_l [NT*FF_];

// ================= helpers =================================================
__device__ __forceinline__ uint32_t smem_u32(const void* p) {
    uint32_t a;
    asm("{ .reg .u64 t; cvta.to.shared.u64 t, %1; cvt.u32.u64 %0, t; }"
        : "=r"(a) : "l"(p));
    return a;
}
__device__ __forceinline__ void cp16(uint32_t dst, const void* src) {
    asm volatile("cp.async.cg.shared.global [%0], [%1], 16;" :: "r"(dst), "l"(src));
}
#define CP_COMMIT()  asm volatile("cp.async.commit_group;" ::: "memory")
#define CP_WAIT0()   asm volatile("cp.async.wait_group 0;" ::: "memory")

#define LDSM4(r0,r1,r2,r3,addr) \
    asm volatile("ldmatrix.sync.aligned.m8n8.x4.shared.b16 {%0,%1,%2,%3}, [%4];" \
        : "=r"(r0), "=r"(r1), "=r"(r2), "=r"(r3) : "r"(addr))

__device__ __forceinline__ void mma_bf16(
    float& d0, float& d1, float& d2, float& d3,
    uint32_t a0, uint32_t a1, uint32_t a2, uint32_t a3,
    uint32_t b0, uint32_t b1)
{
    asm volatile(
        "mma.sync.aligned.m16n8k16.row.col.f32.bf16.bf16.f32 "
        "{%0,%1,%2,%3}, {%4,%5,%6,%7}, {%8,%9}, {%0,%1,%2,%3};"
        : "+f"(d0), "+f"(d1), "+f"(d2), "+f"(d3)
        : "r"(a0), "r"(a1), "r"(a2), "r"(a3), "r"(b0), "r"(b1));
}

// ---------------- split fp32 -> bf16 hi/lo ---------------------------------
__global__ void __launch_bounds__(256) split_kernel(
    const float* __restrict__ in, __nv_bfloat16* __restrict__ hi,
    __nv_bfloat16* __restrict__ lo, int n)
{
    int i = (blockIdx.x * 256 + threadIdx.x) * 4;
    if (i >= n) return;
    float4 v = *(const float4*)(in + i);
    __nv_bfloat16 h0 = __float2bfloat16(v.x);
    __nv_bfloat16 h1 = __float2bfloat16(v.y);
    __nv_bfloat16 h2 = __float2bfloat16(v.z);
    __nv_bfloat16 h3 = __float2bfloat16(v.w);
    __nv_bfloat16 l0 = __float2bfloat16(v.x - __bfloat162float(h0));
    __nv_bfloat16 l1 = __float2bfloat16(v.y - __bfloat162float(h1));
    __nv_bfloat16 l2 = __float2bfloat16(v.z - __bfloat162float(h2));
    __nv_bfloat16 l3 = __float2bfloat16(v.w - __bfloat162float(h3));
    *(__nv_bfloat162*)(hi + i)     = __halves2bfloat162(h0, h1);
    *(__nv_bfloat162*)(hi + i + 2) = __halves2bfloat162(h2, h3);
    *(__nv_bfloat162*)(lo + i)     = __halves2bfloat162(l0, l1);
    *(__nv_bfloat162*)(lo + i + 2) = __halves2bfloat162(l2, l3);
}

// ---------------- HMMA bf16x3 GEMM: C[M,N] = A[M,K] * B[N,K]^T + bias ------
// 128x128 tile, BK=32, 256 threads (8 warps of 64x32).
// SMEM per stage: 4 matrices (Ah,Al,Bh,Bl) of 128 rows x 32 bf16, stride 80B.
#define TSTRIDE   80                       // bytes per row (64 data + 16 pad)
#define TMAT      (128 * TSTRIDE)          // 10240 B per matrix
#define TSTAGE    (4 * TMAT)               // 40960 B per stage
#define GEMM_SMEM (2 * TSTAGE)             // 81920 B

template<int RELU>
__global__ void __launch_bounds__(256, 1) gemm_mma(
    const __nv_bfloat16* __restrict__ Ah, const __nv_bfloat16* __restrict__ Al,
    const __nv_bfloat16* __restrict__ Bh, const __nv_bfloat16* __restrict__ Bl,
    const float* __restrict__ bias, float* __restrict__ C,
    int M, int N, int K)
{
    extern __shared__ char smem[];
    const uint32_t sbase = smem_u32(smem);
    const int tid  = threadIdx.x;
    const int wid  = tid >> 5;
    const int lane = tid & 31;
    const int row0 = blockIdx.y * 128;
    const int col0 = blockIdx.x * 128;
    const int wm   = wid & 1;          // 0..1 -> 64 rows
    const int wn   = wid >> 1;         // 0..3 -> 32 cols

    const __nv_bfloat16* gsrc[4] = {
        Ah + (size_t)row0 * K, Al + (size_t)row0 * K,
        Bh + (size_t)col0 * K, Bl + (size_t)col0 * K };

    // ldmatrix lane addressing (shared by A and B tiles; same pattern)
    const int l_mat = lane >> 3, l_r = lane & 7;
    const int frag_row = l_r + (l_mat & 1) * 8;       // row within 16-row tile
    const int frag_kb  = (l_mat >> 1) * 16;           // byte offset within row

    const int cp_row = tid >> 2;        // 0..63 (x2 passes -> 128 rows)
    const int cp_c   = tid & 3;         // 16B chunk within 64B row

    float acc[4][4][4];
    #pragma unroll
    for (int i = 0; i < 4; i++)
        #pragma unroll
        for (int j = 0; j < 4; j++)
            #pragma unroll
            for (int r = 0; r < 4; r++) acc[i][j][r] = 0.f;

    const int nstage = K >> 5;

    // prefetch stage 0
    {
        #pragma unroll
        for (int m = 0; m < 4; m++) {
            const uint32_t mbuf = sbase + m * TMAT;
            const __nv_bfloat16* g = gsrc[m] + cp_c * 8;
            #pragma unroll
            for (int p = 0; p < 2; p++) {
                int r = cp_row + p * 64;
                cp16(mbuf + r * TSTRIDE + cp_c * 16, g + (size_t)r * K);
            }
        }
        CP_COMMIT();
    }

    for (int s = 0; s < nstage; s++) {
        CP_WAIT0();
        __syncthreads();

        if (s + 1 < nstage) {
            const int k0 = (s + 1) << 5;
            const uint32_t bufb = sbase + ((s + 1) & 1) * TSTAGE;
            #pragma unroll
            for (int m = 0; m < 4; m++) {
                const uint32_t mbuf = bufb + m * TMAT;
                const __nv_bfloat16* g = gsrc[m] + k0 + cp_c * 8;
                #pragma unroll
                for (int p = 0; p < 2; p++) {
                    int r = cp_row + p * 64;
                    cp16(mbuf + r * TSTRIDE + cp_c * 16, g + (size_t)r * K);
                }
            }
            CP_COMMIT();
        }

        const uint32_t buf = sbase + (s & 1) * TSTAGE;
        const uint32_t bAh = buf;
        const uint32_t bAl = buf + TMAT;
        const uint32_t bBh = buf + 2 * TMAT;
        const uint32_t bBl = buf + 3 * TMAT;

        #pragma unroll
        for (int ks = 0; ks < 2; ks++) {
            const int kb = ks * 32 + frag_kb;   // byte offset in row

            uint32_t ah[4][4], al[4][4], bh[2][4], bl[2][4];
            #pragma unroll
            for (int mi = 0; mi < 4; mi++) {
                uint32_t ra = (wm * 64 + mi * 16 + frag_row) * TSTRIDE + kb;
                LDSM4(ah[mi][0], ah[mi][1], ah[mi][2], ah[mi][3], bAh + ra);
                LDSM4(al[mi][0], al[mi][1], al[mi][2], al[mi][3], bAl + ra);
            }
            #pragma unroll
            for (int nb = 0; nb < 2; nb++) {
                uint32_t rb = (wn * 32 + nb * 16 + frag_row) * TSTRIDE + kb;
                LDSM4(bh[nb][0], bh[nb][1], bh[nb][2], bh[nb][3], bBh + rb);
                LDSM4(bl[nb][0], bl[nb][1], bl[nb][2], bl[nb][3], bBl + rb);
            }

            #pragma unroll
            for (int mi = 0; mi < 4; mi++)
                #pragma unroll
                for (int ni = 0; ni < 4; ni++) {
                    const int nb = ni >> 1, no = ni & 1;
                    // hi*hi
                    mma_bf16(acc[mi][ni][0], acc[mi][ni][1],
                             acc[mi][ni][2], acc[mi][ni][3],
                             ah[mi][0], ah[mi][1], ah[mi][2], ah[mi][3],
                             bh[nb][no], bh[nb][no + 2]);
                    // hi*lo
                    mma_bf16(acc[mi][ni][0], acc[mi][ni][1],
                             acc[mi][ni][2], acc[mi][ni][3],
                             ah[mi][0], ah[mi][1], ah[mi][2], ah[mi][3],
                             bl[nb][no], bl[nb][no + 2]);
                    // lo*hi
                    mma_bf16(acc[mi][ni][0], acc[mi][ni][1],
                             acc[mi][ni][2], acc[mi][ni][3],
                             al[mi][0], al[mi][1], al[mi][2], al[mi][3],
                             bh[nb][no], bh[nb][no + 2]);
                }
        }
        __syncthreads();
    }

    // epilogue: direct float2 stores with bias (+relu)
    const int g8  = lane >> 2;      // row group 0..7
    const int tig = lane & 3;       // col pair
    #pragma unroll
    for (int mi = 0; mi < 4; mi++) {
        #pragma unroll
        for (int ni = 0; ni < 4; ni++) {
            int col = col0 + wn * 32 + ni * 8 + tig * 2;
            float2 bs = *(const float2*)(bias + col);
            int r0 = row0 + wm * 64 + mi * 16 + g8;
            float2 v0 = { acc[mi][ni][0] + bs.x, acc[mi][ni][1] + bs.y };
            float2 v1 = { acc[mi][ni][2] + bs.x, acc[mi][ni][3] + bs.y };
            if (RELU) {
                v0.x = fmaxf(v0.x, 0.f); v0.y = fmaxf(v0.y, 0.f);
                v1.x = fmaxf(v1.x, 0.f); v1.y = fmaxf(v1.y, 0.f);
            }
            *(float2*)(C + (size_t)r0 * N + col)       = v0;
            *(float2*)(C + (size_t)(r0 + 8) * N + col) = v1;
        }
    }
}

// ---------------- mask dtype probe ----------------------------------------
__global__ void detect_mask_kernel(const unsigned char* __restrict__ m) {
    __shared__ int f3f, foff;
    if (threadIdx.x == 0) { f3f = 0; foff = 0; }
    __syncthreads();
    int l3f = 0, loff = 0;
    for (int i = threadIdx.x; i < 65536; i += blockDim.x) {
        unsigned char v = m[i];
        if (v == 0x3f) l3f = 1;
        else if (v && (i & 3)) loff = 1;
    }
    if (l3f)  atomicOr(&f3f, 1);
    if (loff) atomicOr(&foff, 1);
    __syncthreads();
    if (threadIdx.x == 0) g_mask_mode = f3f ? 2 : (foff ? 1 : 0);
}

__device__ __forceinline__ float mask_val(const void* mp, int idx) {
    int mode = g_mask_mode;
    if (mode == 0) return ((const int*)mp)[idx] ? 1.f : 0.f;
    if (mode == 1) return ((const unsigned char*)mp)[idx] ? 1.f : 0.f;
    return ((const float*)mp)[idx];
}

// ---------------- attention (flash-style, 64x64 tiles) --------------------
__device__ __forceinline__ float shfl_max16(float v) {
    #pragma unroll
    for (int o = 8; o; o >>= 1) v = fmaxf(v, __shfl_xor_sync(0xffffffffu, v, o, 16));
    return v;
}
__device__ __forceinline__ float shfl_sum16(float v) {
    #pragma unroll
    for (int o = 8; o; o >>= 1) v += __shfl_xor_sync(0xffffffffu, v, o, 16);
    return v;
}

#define ATTN_PAD 65
#define SMEM_ATTN ((4 * 64 * ATTN_PAD + 64) * (int)sizeof(float))

__global__ void __launch_bounds__(256) attn_kernel(
    const float* __restrict__ qkv, const void* __restrict__ mask,
    float* __restrict__ ctx)
{
    const int it = blockIdx.x;
    const int h  = blockIdx.y;
    const int b  = blockIdx.z;

    extern __shared__ float sm[];
    float* Qs = sm;
    float* Ks = Qs + 64 * ATTN_PAD;
    float* Vs = Ks + 64 * ATTN_PAD;
    float* Ps = Vs + 64 * ATTN_PAD;
    float* mk = Ps + 64 * ATTN_PAD;

    const int tid = threadIdx.x;
    const int tx  = tid & 15;
    const int ty  = tid >> 4;
    const float scale = 0.125f;

    const int rowbase = b * S_;
    const int qcol = h * HD_;
    const int i0 = it * 64;

    for (int t = tid; t < 64 * 16; t += 256) {
        int r = t >> 4, c4 = (t & 15) << 2;
        float4 v = *(const float4*)(qkv + (size_t)(rowbase + i0 + r) * (3 * D_) + qcol + c4);
        Qs[r * ATTN_PAD + c4 + 0] = v.x;
        Qs[r * ATTN_PAD + c4 + 1] = v.y;
        Qs[r * ATTN_PAD + c4 + 2] = v.z;
        Qs[r * ATTN_PAD + c4 + 3] = v.w;
    }

    float m_run[4], l_run[4], acc[4][4];
    #pragma unroll
    for (int r = 0; r < 4; r++) {
        m_run[r] = -3.0e38f; l_run[r] = 0.f;
        #pragma unroll
        for (int c = 0; c < 4; c++) acc[r][c] = 0.f;
    }

    for (int j0 = 0; j0 < S_; j0 += 64) {
        __syncthreads();
        for (int t = tid; t < 64 * 16; t += 256) {
            int r = t >> 4, c4 = (t & 15) << 2;
            const float* base = qkv + (size_t)(rowbase + j0 + r) * (3 * D_) + qcol;
            float4 kv = *(const float4*)(base + D_ + c4);
            float4 vv = *(const float4*)(base + 2 * D_ + c4);
            Ks[r * ATTN_PAD + c4 + 0] = kv.x; Ks[r * ATTN_PAD + c4 + 1] = kv.y;
            Ks[r * ATTN_PAD + c4 + 2] = kv.z; Ks[r * ATTN_PAD + c4 + 3] = kv.w;
            Vs[r * ATTN_PAD + c4 + 0] = vv.x; Vs[r * ATTN_PAD + c4 + 1] = vv.y;
            Vs[r * ATTN_PAD + c4 + 2] = vv.z; Vs[r * ATTN_PAD + c4 + 3] = vv.w;
        }
        if (tid < 64) mk[tid] = mask_val(mask, (b * H_ + h) * S_ + j0 + tid);
        __syncthreads();

        float s[4][4];
        #pragma unroll
        for (int r = 0; r < 4; r++)
            #pragma unroll
            for (int c = 0; c < 4; c++) s[r][c] = 0.f;
        #pragma unroll 8
        for (int d = 0; d < 64; d++) {
            float qv[4], kv[4];
            #pragma unroll
            for (int r = 0; r < 4; r++) qv[r] = Qs[(ty * 4 + r) * ATTN_PAD + d];
            #pragma unroll
            for (int c = 0; c < 4; c++) kv[c] = Ks[(tx * 4 + c) * ATTN_PAD + d];
            #pragma unroll
            for (int r = 0; r < 4; r++)
                #pragma unroll
                for (int c = 0; c < 4; c++) s[r][c] = fmaf(qv[r], kv[c], s[r][c]);
        }
        float mkv[4];
        #pragma unroll
        for (int c = 0; c < 4; c++) mkv[c] = mk[tx * 4 + c];
        #pragma unroll
        for (int r = 0; r < 4; r++)
            #pragma unroll
            for (int c = 0; c < 4; c++)
                s[r][c] = (mkv[c] > 0.5f) ? s[r][c] * scale : NEGV;

        float corr[4];
        #pragma unroll
        for (int r = 0; r < 4; r++) {
            float mt = fmaxf(fmaxf(s[r][0], s[r][1]), fmaxf(s[r][2], s[r][3]));
            mt = shfl_max16(mt);
            float nm = fmaxf(m_run[r], mt);
            corr[r] = __expf(m_run[r] - nm);
            m_run[r] = nm;
        }
        #pragma unroll
        for (int r = 0; r < 4; r++) {
            float rs = 0.f;
            #pragma unroll
            for (int c = 0; c < 4; c++) {
                float p = __expf(s[r][c] - m_run[r]);
                Ps[(ty * 4 + r) * ATTN_PAD + tx * 4 + c] = p;
                rs += p;
            }
            rs = shfl_sum16(rs);
            l_run[r] = l_run[r] * corr[r] + rs;
        }
        __syncthreads();

        #pragma unroll
        for (int r = 0; r < 4; r++)
            #pragma unroll
            for (int c = 0; c < 4; c++) acc[r][c] *= corr[r];
        #pragma unroll 8
        for (int j = 0; j < 64; j++) {
            float pv[4], vv[4];
            #pragma unroll
            for (int r = 0; r < 4; r++) pv[r] = Ps[(ty * 4 + r) * ATTN_PAD + j];
            #pragma unroll
            for (int c = 0; c < 4; c++) vv[c] = Vs[j * ATTN_PAD + tx * 4 + c];
            #pragma unroll
            for (int r = 0; r < 4; r++)
                #pragma unroll
                for (int c = 0; c < 4; c++) acc[r][c] = fmaf(pv[r], vv[c], acc[r][c]);
        }
    }

    #pragma unroll
    for (int r = 0; r < 4; r++) {
        float inv = 1.f / l_run[r];
        #pragma unroll
        for (int c = 0; c < 4; c++) {
            ctx[(size_t)(rowbase + i0 + ty * 4 + r) * D_ + qcol + tx * 4 + c] = acc[r][c] * inv;
        }
    }
}

// ---------------- residual + LayerNorm ------------------------------------
__global__ void __launch_bounds__(256) ln_residual_kernel(
    const float* __restrict__ a, const float* __restrict__ res,
    const float* __restrict__ gamma, const float* __restrict__ beta,
    float* __restrict__ out)
{
    const int row = blockIdx.x;
    const int tid = threadIdx.x;
    const float* pa = a   + (size_t)row * D_;
    const float* pr = res + (size_t)row * D_;

    float v[4], sum = 0.f, sq = 0.f;
    #pragma unroll
    for (int i = 0; i < 4; i++) {
        int c = tid + i * 256;
        float t = pa[c] + pr[c];
        v[i] = t; sum += t; sq += t * t;
    }
    #pragma unroll
    for (int o = 16; o; o >>= 1) {
        sum += __shfl_xor_sync(0xffffffffu, sum, o);
        sq  += __shfl_xor_sync(0xffffffffu, sq,  o);
    }
    __shared__ float sh1[8], sh2[8];
    __shared__ float smean, srstd;
    if ((tid & 31) == 0) { sh1[tid >> 5] = sum; sh2[tid >> 5] = sq; }
    __syncthreads();
    if (tid == 0) {
        float s = 0.f, s2 = 0.f;
        #pragma unroll
        for (int i = 0; i < 8; i++) { s += sh1[i]; s2 += sh2[i]; }
        float mean = s * (1.f / D_);
        float var  = s2 * (1.f / D_) - mean * mean;
        smean = mean;
        srstd = rsqrtf(var + 1e-12f);
    }
    __syncthreads();
    float mean = smean, rstd = srstd;
    #pragma unroll
    for (int i = 0; i < 4; i++) {
        int c = tid + i * 256;
        out[(size_t)row * D_ + c] = gamma[c] * (v[i] - mean) * rstd + beta[c];
    }
}

// ---------------- launch ---------------------------------------------------
static inline void split_launch(const float* in, __nv_bfloat16* hi,
                                __nv_bfloat16* lo, int n) {
    split_kernel<<<(n / 4 + 255) / 256, 256>>>(in, hi, lo, n);
}

extern "C" void kernel_launch(void* const* d_in, const int* in_sizes, int n_in,
                              void* d_out, int out_size)
{
    const float* x    = (const float*)d_in[0];
    const void*  mask = d_in[1];
    const float* Wqkv = (const float*)d_in[2];
    const float* bqkv = (const float*)d_in[3];
    const float* Wo   = (const float*)d_in[4];
    const float* bo   = (const float*)d_in[5];
    const float* W1   = (const float*)d_in[6];
    const float* b1   = (const float*)d_in[7];
    const float* W2   = (const float*)d_in[8];
    const float* b2   = (const float*)d_in[9];
    const float* g1   = (const float*)d_in[10];
    const float* be1  = (const float*)d_in[11];
    const float* g2   = (const float*)d_in[12];
    const float* be2  = (const float*)d_in[13];
    float* out = (float*)d_out;

    float *qkv, *ctx, *attn, *hbuf, *f1, *f2;
    cudaGetSymbolAddress((void**)&qkv,  g_qkv);
    cudaGetSymbolAddress((void**)&ctx,  g_ctx);
    cudaGetSymbolAddress((void**)&attn, g_attn);
    cudaGetSymbolAddress((void**)&hbuf, g_h);
    cudaGetSymbolAddress((void**)&f1,   g_ffn1);
    cudaGetSymbolAddress((void**)&f2,   g_ffn2);

    __nv_bfloat16 *wqh, *wql, *woh, *wol, *w1h, *w1l, *w2h, *w2l, *ah, *al;
    cudaGetSymbolAddress((void**)&wqh, g_wqkv_h); cudaGetSymbolAddress((void**)&wql, g_wqkv_l);
    cudaGetSymbolAddress((void**)&woh, g_wo_h);   cudaGetSymbolAddress((void**)&wol, g_wo_l);
    cudaGetSymbolAddress((void**)&w1h, g_w1_h);   cudaGetSymbolAddress((void**)&w1l, g_w1_l);
    cudaGetSymbolAddress((void**)&w2h, g_w2_h);   cudaGetSymbolAddress((void**)&w2l, g_w2_l);
    cudaGetSymbolAddress((void**)&ah,  g_act_h);  cudaGetSymbolAddress((void**)&al,  g_act_l);

    cudaFuncSetAttribute(attn_kernel,
                         cudaFuncAttributeMaxDynamicSharedMemorySize, SMEM_ATTN);
    cudaFuncSetAttribute(gemm_mma<0>,
                         cudaFuncAttributeMaxDynamicSharedMemorySize, GEMM_SMEM);
    cudaFuncSetAttribute(gemm_mma<1>,
                         cudaFuncAttributeMaxDynamicSharedMemorySize, GEMM_SMEM);

    detect_mask_kernel<<<1, 256>>>((const unsigned char*)mask);

    // weight splits
    split_launch(Wqkv, wqh, wql, 3 * D_ * D_);
    split_launch(Wo,   woh, wol, D_ * D_);
    split_launch(W1,   w1h, w1l, FF_ * D_);
    split_launch(W2,   w2h, w2l, D_ * FF_);

    // qkv = x @ Wqkv^T + bqkv : [4096, 3072]
    split_launch(x, ah, al, NT * D_);
    gemm_mma<0><<<dim3(3 * D_ / 128, NT / 128), 256, GEMM_SMEM>>>(
        ah, al, wqh, wql, bqkv, qkv, NT, 3 * D_, D_);

    // attention -> ctx [4096, 1024]
    attn_kernel<<<dim3(S_ / 64, H_, B_), 256, SMEM_ATTN>>>(qkv, mask, ctx);

    // attn_out = ctx @ Wo^T + bo
    split_launch(ctx, ah, al, NT * D_);
    gemm_mma<0><<<dim3(D_ / 128, NT / 128), 256, GEMM_SMEM>>>(
        ah, al, woh, wol, bo, attn, NT, D_, D_);

    // h = LN1(attn_out + x)
    ln_residual_kernel<<<NT, 256>>>(attn, x, g1, be1, hbuf);

    // ffn1 = relu(h @ W1^T + b1) : [4096, 4096]
    split_launch(hbuf, ah, al, NT * D_);
    gemm_mma<1><<<dim3(FF_ / 128, NT / 128), 256, GEMM_SMEM>>>(
        ah, al, w1h, w1l, b1, f1, NT, FF_, D_);

    // ffn2 = ffn1 @ W2^T + b2 : [4096, 1024]
    split_launch(f1, ah, al, NT * FF_);
    gemm_mma<0><<<dim3(D_ / 128, NT / 128), 256, GEMM_SMEM>>>(
        ah, al, w2h, w2l, b2, f2, NT, D_, FF_);

    // out = LN2(ffn2 + h)
    ln_residual_kernel<<<NT, 256>>>(f2, hbuf, g2, be2, out);
}

// round 4
// speedup vs baseline: 2.1781x; 1.1896x over previous
#include <cuda_runtime.h>
#include <cuda_bf16.h>
#include <math.h>
#include <stdint.h>

#define B_   4
#define S_   1024
#define D_   1024
#define H_   16
#define HD_  64
#define FF_  4096
#define NT   (B_*S_)
#define NEGV (-1e9f)

// ---------------- scratch -------------------------------------------------
__device__ float g_attn[NT * D_];
__device__ float g_h   [NT * D_];
__device__ float g_ffn2[NT * D_];
__device__ int   g_mask_mode;

__device__ __nv_bfloat16 g_wqkv_h[3*D_*D_], g_wqkv_l[3*D_*D_];
__device__ __nv_bfloat16 g_wo_h  [D_*D_],   g_wo_l  [D_*D_];
__device__ __nv_bfloat16 g_w1_h  [FF_*D_],  g_w1_l  [FF_*D_];
__device__ __nv_bfloat16 g_w2_h  [D_*FF_],  g_w2_l  [D_*FF_];
__device__ __nv_bfloat16 g_act_h [NT*FF_],  g_act_l [NT*FF_];   // x-split, then f1
__device__ __nv_bfloat16 g_qkv_h [NT*3*D_], g_qkv_l [NT*3*D_];
__device__ __nv_bfloat16 g_ctx_h [NT*D_],   g_ctx_l [NT*D_];
__device__ __nv_bfloat16 g_h_h   [NT*D_],   g_h_l   [NT*D_];

// ================= helpers =================================================
__device__ __forceinline__ uint32_t smem_u32(const void* p) {
    uint32_t a;
    asm("{ .reg .u64 t; cvta.to.shared.u64 t, %1; cvt.u32.u64 %0, t; }"
        : "=r"(a) : "l"(p));
    return a;
}
__device__ __forceinline__ void cp16(uint32_t dst, const void* src) {
    asm volatile("cp.async.cg.shared.global [%0], [%1], 16;" :: "r"(dst), "l"(src));
}
#define CP_COMMIT() asm volatile("cp.async.commit_group;" ::: "memory")
#define CP_WAIT0()  asm volatile("cp.async.wait_group 0;" ::: "memory")
#define CP_WAIT1()  asm volatile("cp.async.wait_group 1;" ::: "memory")

#define LDSM4(r0,r1,r2,r3,addr) \
    asm volatile("ldmatrix.sync.aligned.m8n8.x4.shared.b16 {%0,%1,%2,%3}, [%4];" \
        : "=r"(r0), "=r"(r1), "=r"(r2), "=r"(r3) : "r"(addr))
#define LDSM4T(r0,r1,r2,r3,addr) \
    asm volatile("ldmatrix.sync.aligned.m8n8.x4.trans.shared.b16 {%0,%1,%2,%3}, [%4];" \
        : "=r"(r0), "=r"(r1), "=r"(r2), "=r"(r3) : "r"(addr))

__device__ __forceinline__ void mma_bf16(
    float& d0, float& d1, float& d2, float& d3,
    uint32_t a0, uint32_t a1, uint32_t a2, uint32_t a3,
    uint32_t b0, uint32_t b1)
{
    asm volatile(
        "mma.sync.aligned.m16n8k16.row.col.f32.bf16.bf16.f32 "
        "{%0,%1,%2,%3}, {%4,%5,%6,%7}, {%8,%9}, {%0,%1,%2,%3};"
        : "+f"(d0), "+f"(d1), "+f"(d2), "+f"(d3)
        : "r"(a0), "r"(a1), "r"(a2), "r"(a3), "r"(b0), "r"(b1));
}

__device__ __forceinline__ void split_pack(float a, float b,
                                           uint32_t& hi, uint32_t& lo) {
    __nv_bfloat16 ha = __float2bfloat16(a), hb = __float2bfloat16(b);
    __nv_bfloat16 la = __float2bfloat16(a - __bfloat162float(ha));
    __nv_bfloat16 lb = __float2bfloat16(b - __bfloat162float(hb));
    __nv_bfloat162 Hh = __halves2bfloat162(ha, hb);
    __nv_bfloat162 Ll = __halves2bfloat162(la, lb);
    hi = *(uint32_t*)&Hh; lo = *(uint32_t*)&Ll;
}

// ---------------- split fp32 -> bf16 hi/lo ---------------------------------
__global__ void __launch_bounds__(256) split_kernel(
    const float* __restrict__ in, __nv_bfloat16* __restrict__ hi,
    __nv_bfloat16* __restrict__ lo, int n)
{
    int i = (blockIdx.x * 256 + threadIdx.x) * 4;
    if (i >= n) return;
    float4 v = *(const float4*)(in + i);
    uint32_t h0, l0, h1, l1;
    split_pack(v.x, v.y, h0, l0);
    split_pack(v.z, v.w, h1, l1);
    *(uint32_t*)(hi + i)     = h0;  *(uint32_t*)(hi + i + 2) = h1;
    *(uint32_t*)(lo + i)     = l0;  *(uint32_t*)(lo + i + 2) = l1;
}

// ---------------- HMMA bf16x3 GEMM -----------------------------------------
#define TSTRIDE   80
#define TMAT      (128 * TSTRIDE)
#define TSTAGE    (4 * TMAT)
#define GEMM_SMEM (2 * TSTAGE)

template<int RELU, int SPLIT>
__global__ void __launch_bounds__(256, 1) gemm_mma(
    const __nv_bfloat16* __restrict__ Ah, const __nv_bfloat16* __restrict__ Al,
    const __nv_bfloat16* __restrict__ Bh, const __nv_bfloat16* __restrict__ Bl,
    const float* __restrict__ bias, float* __restrict__ C,
    __nv_bfloat16* __restrict__ Ch, __nv_bfloat16* __restrict__ Cl,
    int M, int N, int K)
{
    extern __shared__ char smem[];
    const uint32_t sbase = smem_u32(smem);
    const int tid  = threadIdx.x;
    const int wid  = tid >> 5;
    const int lane = tid & 31;
    const int row0 = blockIdx.y * 128;
    const int col0 = blockIdx.x * 128;
    const int wm   = wid & 1;
    const int wn   = wid >> 1;

    const __nv_bfloat16* gsrc[4] = {
        Ah + (size_t)row0 * K, Al + (size_t)row0 * K,
        Bh + (size_t)col0 * K, Bl + (size_t)col0 * K };

    const int l_mat = lane >> 3, l_r = lane & 7;
    const int frag_row = l_r + (l_mat & 1) * 8;
    const int frag_kb  = (l_mat >> 1) * 16;

    const int cp_row = tid >> 2;
    const int cp_c   = tid & 3;

    float acc[4][4][4];
    #pragma unroll
    for (int i = 0; i < 4; i++)
        #pragma unroll
        for (int j = 0; j < 4; j++)
            #pragma unroll
            for (int r = 0; r < 4; r++) acc[i][j][r] = 0.f;

    const int nstage = K >> 5;

    {
        #pragma unroll
        for (int m = 0; m < 4; m++) {
            const uint32_t mbuf = sbase + m * TMAT;
            const __nv_bfloat16* g = gsrc[m] + cp_c * 8;
            #pragma unroll
            for (int p = 0; p < 2; p++) {
                int r = cp_row + p * 64;
                cp16(mbuf + r * TSTRIDE + cp_c * 16, g + (size_t)r * K);
            }
        }
        CP_COMMIT();
    }

    for (int s = 0; s < nstage; s++) {
        CP_WAIT0();
        __syncthreads();

        if (s + 1 < nstage) {
            const int k0 = (s + 1) << 5;
            const uint32_t bufb = sbase + ((s + 1) & 1) * TSTAGE;
            #pragma unroll
            for (int m = 0; m < 4; m++) {
                const uint32_t mbuf = bufb + m * TMAT;
                const __nv_bfloat16* g = gsrc[m] + k0 + cp_c * 8;
                #pragma unroll
                for (int p = 0; p < 2; p++) {
                    int r = cp_row + p * 64;
                    cp16(mbuf + r * TSTRIDE + cp_c * 16, g + (size_t)r * K);
                }
            }
            CP_COMMIT();
        }

        const uint32_t buf = sbase + (s & 1) * TSTAGE;
        const uint32_t bAh = buf;
        const uint32_t bAl = buf + TMAT;
        const uint32_t bBh = buf + 2 * TMAT;
        const uint32_t bBl = buf + 3 * TMAT;

        #pragma unroll
        for (int ks = 0; ks < 2; ks++) {
            const int kb = ks * 32 + frag_kb;

            uint32_t ah[4][4], al[4][4], bh[2][4], bl[2][4];
            #pragma unroll
            for (int mi = 0; mi < 4; mi++) {
                uint32_t ra = (wm * 64 + mi * 16 + frag_row) * TSTRIDE + kb;
                LDSM4(ah[mi][0], ah[mi][1], ah[mi][2], ah[mi][3], bAh + ra);
                LDSM4(al[mi][0], al[mi][1], al[mi][2], al[mi][3], bAl + ra);
            }
            #pragma unroll
            for (int nb = 0; nb < 2; nb++) {
                uint32_t rb = (wn * 32 + nb * 16 + frag_row) * TSTRIDE + kb;
                LDSM4(bh[nb][0], bh[nb][1], bh[nb][2], bh[nb][3], bBh + rb);
                LDSM4(bl[nb][0], bl[nb][1], bl[nb][2], bl[nb][3], bBl + rb);
            }

            #pragma unroll
            for (int mi = 0; mi < 4; mi++)
                #pragma unroll
                for (int ni = 0; ni < 4; ni++) {
                    const int nb = ni >> 1, no = ni & 1;
                    mma_bf16(acc[mi][ni][0], acc[mi][ni][1],
                             acc[mi][ni][2], acc[mi][ni][3],
                             ah[mi][0], ah[mi][1], ah[mi][2], ah[mi][3],
                             bh[nb][no], bh[nb][no + 2]);
                    mma_bf16(acc[mi][ni][0], acc[mi][ni][1],
                             acc[mi][ni][2], acc[mi][ni][3],
                             ah[mi][0], ah[mi][1], ah[mi][2], ah[mi][3],
                             bl[nb][no], bl[nb][no + 2]);
                    mma_bf16(acc[mi][ni][0], acc[mi][ni][1],
                             acc[mi][ni][2], acc[mi][ni][3],
                             al[mi][0], al[mi][1], al[mi][2], al[mi][3],
                             bh[nb][no], bh[nb][no + 2]);
                }
        }
        __syncthreads();
    }

    const int g8  = lane >> 2;
    const int tig = lane & 3;
    #pragma unroll
    for (int mi = 0; mi < 4; mi++) {
        #pragma unroll
        for (int ni = 0; ni < 4; ni++) {
            int col = col0 + wn * 32 + ni * 8 + tig * 2;
            float2 bs = *(const float2*)(bias + col);
            int r0 = row0 + wm * 64 + mi * 16 + g8;
            float2 v0 = { acc[mi][ni][0] + bs.x, acc[mi][ni][1] + bs.y };
            float2 v1 = { acc[mi][ni][2] + bs.x, acc[mi][ni][3] + bs.y };
            if (RELU) {
                v0.x = fmaxf(v0.x, 0.f); v0.y = fmaxf(v0.y, 0.f);
                v1.x = fmaxf(v1.x, 0.f); v1.y = fmaxf(v1.y, 0.f);
            }
            if (SPLIT) {
                uint32_t h0, l0, h1, l1;
                split_pack(v0.x, v0.y, h0, l0);
                split_pack(v1.x, v1.y, h1, l1);
                *(uint32_t*)(Ch + (size_t)r0 * N + col)       = h0;
                *(uint32_t*)(Cl + (size_t)r0 * N + col)       = l0;
                *(uint32_t*)(Ch + (size_t)(r0 + 8) * N + col) = h1;
                *(uint32_t*)(Cl + (size_t)(r0 + 8) * N + col) = l1;
            } else {
                *(float2*)(C + (size_t)r0 * N + col)       = v0;
                *(float2*)(C + (size_t)(r0 + 8) * N + col) = v1;
            }
        }
    }
}

// ---------------- mask dtype probe ----------------------------------------
__global__ void detect_mask_kernel(const unsigned char* __restrict__ m) {
    __shared__ int f3f, foff;
    if (threadIdx.x == 0) { f3f = 0; foff = 0; }
    __syncthreads();
    int l3f = 0, loff = 0;
    for (int i = threadIdx.x; i < 65536; i += blockDim.x) {
        unsigned char v = m[i];
        if (v == 0x3f) l3f = 1;
        else if (v && (i & 3)) loff = 1;
    }
    if (l3f)  atomicOr(&f3f, 1);
    if (loff) atomicOr(&foff, 1);
    __syncthreads();
    if (threadIdx.x == 0) g_mask_mode = f3f ? 2 : (foff ? 1 : 0);
}

__device__ __forceinline__ float mask_val(const void* mp, int idx) {
    int mode = g_mask_mode;
    if (mode == 0) return ((const int*)mp)[idx] ? 1.f : 0.f;
    if (mode == 1) return ((const unsigned char*)mp)[idx] ? 1.f : 0.f;
    return ((const float*)mp)[idx];
}

// ---------------- tensor-core flash attention ------------------------------
// Br=128 (8 warps x 16 rows), Bc=64, bf16x3 QK^T and PV, fp32 softmax.
#define ASTRIDE 144
#define KVMAT   (64 * ASTRIDE)
#define KVSTAGE (4 * KVMAT)
#define SMEM_ATTN (2 * 128 * ASTRIDE + 2 * KVSTAGE + S_ * 4)

__device__ __forceinline__ void kv_prefetch(
    uint32_t sKV, int stg, int jb, int tid, int rowbase, int h,
    const __nv_bfloat16* QKVh, const __nv_bfloat16* QKVl)
{
    const uint32_t base = sKV + stg * KVSTAGE;
    const int r  = tid >> 2;
    const int c0 = tid & 3;
    const size_t go = (size_t)(rowbase + jb * 64 + r) * (3 * D_) + h * HD_;
    const __nv_bfloat16* srcs[4] = {
        QKVh + go + D_, QKVl + go + D_, QKVh + go + 2 * D_, QKVl + go + 2 * D_ };
    #pragma unroll
    for (int m = 0; m < 4; m++) {
        const uint32_t mb = base + m * KVMAT + r * ASTRIDE;
        cp16(mb + c0 * 16,       srcs[m] + c0 * 8);
        cp16(mb + (c0 + 4) * 16, srcs[m] + (c0 + 4) * 8);
    }
}

__global__ void __launch_bounds__(256, 1) attn_mma_kernel(
    const __nv_bfloat16* __restrict__ QKVh, const __nv_bfloat16* __restrict__ QKVl,
    const void* __restrict__ mask,
    __nv_bfloat16* __restrict__ Ch, __nv_bfloat16* __restrict__ Cl)
{
    const int it = blockIdx.x, h = blockIdx.y, b = blockIdx.z;
    extern __shared__ char sm8[];
    const uint32_t sb = smem_u32(sm8);
    const uint32_t sQH = sb, sQL = sb + 128 * ASTRIDE;
    const uint32_t sKV = sb + 2 * 128 * ASTRIDE;
    float* mk = (float*)(sm8 + 2 * 128 * ASTRIDE + 2 * KVSTAGE);

    const int tid = threadIdx.x, w = tid >> 5, lane = tid & 31;
    const int i0 = it * 128, rowbase = b * S_;
    const int frag_row = (lane & 7) + ((lane >> 3) & 1) * 8;
    const int frag_kb  = (lane >> 4) * 16;
    const float scale = 0.125f;

    // Q tile loads (128 rows x 64 bf16, hi+lo)
    {
        int r = tid >> 1;
        const size_t go = (size_t)(rowbase + i0 + r) * (3 * D_) + h * HD_;
        #pragma unroll
        for (int c = 0; c < 4; c++) {
            int ch = (tid & 1) * 4 + c;
            cp16(sQH + r * ASTRIDE + ch * 16, QKVh + go + ch * 8);
            cp16(sQL + r * ASTRIDE + ch * 16, QKVl + go + ch * 8);
        }
    }
    for (int i = tid; i < S_; i += 256)
        mk[i] = mask_val(mask, (b * H_ + h) * S_ + i);

    kv_prefetch(sKV, 0, 0, tid, rowbase, h, QKVh, QKVl);
    CP_COMMIT();
    CP_WAIT0();
    __syncthreads();

    // persistent Q fragments
    uint32_t qh[4][4], ql[4][4];
    #pragma unroll
    for (int kk = 0; kk < 4; kk++) {
        uint32_t a = (w * 16 + frag_row) * ASTRIDE + kk * 32 + frag_kb;
        LDSM4(qh[kk][0], qh[kk][1], qh[kk][2], qh[kk][3], sQH + a);
        LDSM4(ql[kk][0], ql[kk][1], ql[kk][2], ql[kk][3], sQL + a);
    }

    float m_run[2] = { -3.0e38f, -3.0e38f };
    float l_run[2] = { 0.f, 0.f };
    float o[8][4];
    #pragma unroll
    for (int d = 0; d < 8; d++)
        #pragma unroll
        for (int r = 0; r < 4; r++) o[d][r] = 0.f;

    for (int jb = 0; jb < S_ / 64; jb++) {
        if (jb + 1 < S_ / 64) {
            kv_prefetch(sKV, (jb + 1) & 1, jb + 1, tid, rowbase, h, QKVh, QKVl);
            CP_COMMIT();
            CP_WAIT1();
        } else {
            CP_WAIT0();
        }
        __syncthreads();

        const uint32_t kvb = sKV + (jb & 1) * KVSTAGE;
        const uint32_t bKH = kvb, bKL = kvb + KVMAT;
        const uint32_t bVH = kvb + 2 * KVMAT, bVL = kvb + 3 * KVMAT;

        // ---- S = Q K^T (bf16x3) ----
        float s[8][4];
        #pragma unroll
        for (int t = 0; t < 8; t++)
            #pragma unroll
            for (int r = 0; r < 4; r++) s[t][r] = 0.f;

        #pragma unroll
        for (int kk = 0; kk < 4; kk++) {
            #pragma unroll
            for (int nb = 0; nb < 4; nb++) {
                uint32_t kh0, kh1, kh2, kh3, kl0, kl1, kl2, kl3;
                uint32_t ad = (nb * 16 + frag_row) * ASTRIDE + kk * 32 + frag_kb;
                LDSM4(kh0, kh1, kh2, kh3, bKH + ad);
                LDSM4(kl0, kl1, kl2, kl3, bKL + ad);
                const int t0 = nb * 2, t1 = nb * 2 + 1;
                mma_bf16(s[t0][0], s[t0][1], s[t0][2], s[t0][3],
                         qh[kk][0], qh[kk][1], qh[kk][2], qh[kk][3], kh0, kh2);
                mma_bf16(s[t0][0], s[t0][1], s[t0][2], s[t0][3],
                         qh[kk][0], qh[kk][1], qh[kk][2], qh[kk][3], kl0, kl2);
                mma_bf16(s[t0][0], s[t0][1], s[t0][2], s[t0][3],
                         ql[kk][0], ql[kk][1], ql[kk][2], ql[kk][3], kh0, kh2);
                mma_bf16(s[t1][0], s[t1][1], s[t1][2], s[t1][3],
                         qh[kk][0], qh[kk][1], qh[kk][2], qh[kk][3], kh1, kh3);
                mma_bf16(s[t1][0], s[t1][1], s[t1][2], s[t1][3],
                         qh[kk][0], qh[kk][1], qh[kk][2], qh[kk][3], kl1, kl3);
                mma_bf16(s[t1][0], s[t1][1], s[t1][2], s[t1][3],
                         ql[kk][0], ql[kk][1], ql[kk][2], ql[kk][3], kh1, kh3);
            }
        }

        // ---- mask + scale ----
        #pragma unroll
        for (int t = 0; t < 8; t++) {
            float mv0 = mk[jb * 64 + t * 8 + (lane & 3) * 2];
            float mv1 = mk[jb * 64 + t * 8 + (lane & 3) * 2 + 1];
            s[t][0] = (mv0 > 0.5f) ? s[t][0] * scale : NEGV;
            s[t][1] = (mv1 > 0.5f) ? s[t][1] * scale : NEGV;
            s[t][2] = (mv0 > 0.5f) ? s[t][2] * scale : NEGV;
            s[t][3] = (mv1 > 0.5f) ? s[t][3] * scale : NEGV;
        }

        // ---- online softmax ----
        float mx0 = -3.0e38f, mx1 = -3.0e38f;
        #pragma unroll
        for (int t = 0; t < 8; t++) {
            mx0 = fmaxf(mx0, fmaxf(s[t][0], s[t][1]));
            mx1 = fmaxf(mx1, fmaxf(s[t][2], s[t][3]));
        }
        mx0 = fmaxf(mx0, __shfl_xor_sync(0xffffffffu, mx0, 1));
        mx0 = fmaxf(mx0, __shfl_xor_sync(0xffffffffu, mx0, 2));
        mx1 = fmaxf(mx1, __shfl_xor_sync(0xffffffffu, mx1, 1));
        mx1 = fmaxf(mx1, __shfl_xor_sync(0xffffffffu, mx1, 2));
        float nm0 = fmaxf(m_run[0], mx0), nm1 = fmaxf(m_run[1], mx1);
        float corr0 = __expf(m_run[0] - nm0), corr1 = __expf(m_run[1] - nm1);
        m_run[0] = nm0; m_run[1] = nm1;

        float sum0 = 0.f, sum1 = 0.f;
        #pragma unroll
        for (int t = 0; t < 8; t++) {
            s[t][0] = __expf(s[t][0] - nm0); sum0 += s[t][0];
            s[t][1] = __expf(s[t][1] - nm0); sum0 += s[t][1];
            s[t][2] = __expf(s[t][2] - nm1); sum1 += s[t][2];
            s[t][3] = __expf(s[t][3] - nm1); sum1 += s[t][3];
        }
        sum0 += __shfl_xor_sync(0xffffffffu, sum0, 1);
        sum0 += __shfl_xor_sync(0xffffffffu, sum0, 2);
        sum1 += __shfl_xor_sync(0xffffffffu, sum1, 1);
        sum1 += __shfl_xor_sync(0xffffffffu, sum1, 2);
        l_run[0] = l_run[0] * corr0 + sum0;
        l_run[1] = l_run[1] * corr1 + sum1;

        #pragma unroll
        for (int d = 0; d < 8; d++) {
            o[d][0] *= corr0; o[d][1] *= corr0;
            o[d][2] *= corr1; o[d][3] *= corr1;
        }

        // ---- O += P V (split P exact, bf16x3) ----
        #pragma unroll
        for (int kk = 0; kk < 4; kk++) {
            const int t0 = kk * 2, t1 = kk * 2 + 1;
            uint32_t pah[4], pal[4];
            split_pack(s[t0][0], s[t0][1], pah[0], pal[0]);
            split_pack(s[t0][2], s[t0][3], pah[1], pal[1]);
            split_pack(s[t1][0], s[t1][1], pah[2], pal[2]);
            split_pack(s[t1][2], s[t1][3], pah[3], pal[3]);

            const uint32_t vrow =
                (kk * 16 + ((lane >> 3) & 1) * 8 + (lane & 7)) * ASTRIDE +
                (lane >> 4) * 16;
            #pragma unroll
            for (int q = 0; q < 4; q++) {
                uint32_t vh0, vh1, vh2, vh3, vl0, vl1, vl2, vl3;
                LDSM4T(vh0, vh1, vh2, vh3, bVH + vrow + q * 32);
                LDSM4T(vl0, vl1, vl2, vl3, bVL + vrow + q * 32);
                const int d0 = q * 2, d1 = q * 2 + 1;
                mma_bf16(o[d0][0], o[d0][1], o[d0][2], o[d0][3],
                         pah[0], pah[1], pah[2], pah[3], vh0, vh1);
                mma_bf16(o[d0][0], o[d0][1], o[d0][2], o[d0][3],
                         pah[0], pah[1], pah[2], pah[3], vl0, vl1);
                mma_bf16(o[d0][0], o[d0][1], o[d0][2], o[d0][3],
                         pal[0], pal[1], pal[2], pal[3], vh0, vh1);
                mma_bf16(o[d1][0], o[d1][1], o[d1][2], o[d1][3],
                         pah[0], pah[1], pah[2], pah[3], vh2, vh3);
                mma_bf16(o[d1][0], o[d1][1], o[d1][2], o[d1][3],
                         pah[0], pah[1], pah[2], pah[3], vl2, vl3);
                mma_bf16(o[d1][0], o[d1][1], o[d1][2], o[d1][3],
                         pal[0], pal[1], pal[2], pal[3], vh2, vh3);
            }
        }
        __syncthreads();   // stage consumed; safe to overwrite next iter
    }

    // ---- epilogue: ctx hi/lo ----
    const float inv0 = 1.f / l_run[0], inv1 = 1.f / l_run[1];
    const int tok0 = rowbase + i0 + w * 16 + (lane >> 2);
    #pragma unroll
    for (int d = 0; d < 8; d++) {
        int col = h * HD_ + d * 8 + (lane & 3) * 2;
        uint32_t h0, l0, h1, l1;
        split_pack(o[d][0] * inv0, o[d][1] * inv0, h0, l0);
        split_pack(o[d][2] * inv1, o[d][3] * inv1, h1, l1);
        *(uint32_t*)(Ch + (size_t)tok0 * D_ + col)       = h0;
        *(uint32_t*)(Cl + (size_t)tok0 * D_ + col)       = l0;
        *(uint32_t*)(Ch + (size_t)(tok0 + 8) * D_ + col) = h1;
        *(uint32_t*)(Cl + (size_t)(tok0 + 8) * D_ + col) = l1;
    }
}

// ---------------- residual + LayerNorm (optionally emits hi/lo) ------------
template<int SPLIT>
__global__ void __launch_bounds__(256) ln_residual_kernel(
    const float* __restrict__ a, const float* __restrict__ res,
    const float* __restrict__ gamma, const float* __restrict__ beta,
    float* __restrict__ out,
    __nv_bfloat16* __restrict__ oh, __nv_bfloat16* __restrict__ ol)
{
    const int row = blockIdx.x;
    const int tid = threadIdx.x;
    const float* pa = a   + (size_t)row * D_;
    const float* pr = res + (size_t)row * D_;

    float v[4], sum = 0.f, sq = 0.f;
    #pragma unroll
    for (int i = 0; i < 4; i++) {
        int c = tid + i * 256;
        float t = pa[c] + pr[c];
        v[i] = t; sum += t; sq += t * t;
    }
    #pragma unroll
    for (int o2 = 16; o2; o2 >>= 1) {
        sum += __shfl_xor_sync(0xffffffffu, sum, o2);
        sq  += __shfl_xor_sync(0xffffffffu, sq,  o2);
    }
    __shared__ float sh1[8], sh2[8];
    __shared__ float smean, srstd;
    if ((tid & 31) == 0) { sh1[tid >> 5] = sum; sh2[tid >> 5] = sq; }
    __syncthreads();
    if (tid == 0) {
        float s = 0.f, s2 = 0.f;
        #pragma unroll
        for (int i = 0; i < 8; i++) { s += sh1[i]; s2 += sh2[i]; }
        float mean = s * (1.f / D_);
        float var  = s2 * (1.f / D_) - mean * mean;
        smean = mean;
        srstd = rsqrtf(var + 1e-12f);
    }
    __syncthreads();
    float mean = smean, rstd = srstd;
    #pragma unroll
    for (int i = 0; i < 4; i++) {
        int c = tid + i * 256;
        float r = gamma[c] * (v[i] - mean) * rstd + beta[c];
        out[(size_t)row * D_ + c] = r;
        if (SPLIT) {
            __nv_bfloat16 hb = __float2bfloat16(r);
            oh[(size_t)row * D_ + c] = hb;
            ol[(size_t)row * D_ + c] = __float2bfloat16(r - __bfloat162float(hb));
        }
    }
}

// ---------------- launch ---------------------------------------------------
static inline void split_launch(const float* in, __nv_bfloat16* hi,
                                __nv_bfloat16* lo, int n) {
    split_kernel<<<(n / 4 + 255) / 256, 256>>>(in, hi, lo, n);
}

extern "C" void kernel_launch(void* const* d_in, const int* in_sizes, int n_in,
                              void* d_out, int out_size)
{
    const float* x    = (const float*)d_in[0];
    const void*  mask = d_in[1];
    const float* Wqkv = (const float*)d_in[2];
    const float* bqkv = (const float*)d_in[3];
    const float* Wo   = (const float*)d_in[4];
    const float* bo   = (const float*)d_in[5];
    const float* W1   = (const float*)d_in[6];
    const float* b1   = (const float*)d_in[7];
    const float* W2   = (const float*)d_in[8];
    const float* b2   = (const float*)d_in[9];
    const float* g1   = (const float*)d_in[10];
    const float* be1  = (const float*)d_in[11];
    const float* g2   = (const float*)d_in[12];
    const float* be2  = (const float*)d_in[13];
    float* out = (float*)d_out;

    float *attn, *hbuf, *f2;
    cudaGetSymbolAddress((void**)&attn, g_attn);
    cudaGetSymbolAddress((void**)&hbuf, g_h);
    cudaGetSymbolAddress((void**)&f2,   g_ffn2);

    __nv_bfloat16 *wqh, *wql, *woh, *wol, *w1h, *w1l, *w2h, *w2l;
    __nv_bfloat16 *ah, *al, *qh, *ql, *ch, *cl, *hh, *hl;
    cudaGetSymbolAddress((void**)&wqh, g_wqkv_h); cudaGetSymbolAddress((void**)&wql, g_wqkv_l);
    cudaGetSymbolAddress((void**)&woh, g_wo_h);   cudaGetSymbolAddress((void**)&wol, g_wo_l);
    cudaGetSymbolAddress((void**)&w1h, g_w1_h);   cudaGetSymbolAddress((void**)&w1l, g_w1_l);
    cudaGetSymbolAddress((void**)&w2h, g_w2_h);   cudaGetSymbolAddress((void**)&w2l, g_w2_l);
    cudaGetSymbolAddress((void**)&ah,  g_act_h);  cudaGetSymbolAddress((void**)&al,  g_act_l);
    cudaGetSymbolAddress((void**)&qh,  g_qkv_h);  cudaGetSymbolAddress((void**)&ql,  g_qkv_l);
    cudaGetSymbolAddress((void**)&ch,  g_ctx_h);  cudaGetSymbolAddress((void**)&cl,  g_ctx_l);
    cudaGetSymbolAddress((void**)&hh,  g_h_h);    cudaGetSymbolAddress((void**)&hl,  g_h_l);

    cudaFuncSetAttribute(attn_mma_kernel,
                         cudaFuncAttributeMaxDynamicSharedMemorySize, SMEM_ATTN);
    cudaFuncSetAttribute(gemm_mma<0,0>,
                         cudaFuncAttributeMaxDynamicSharedMemorySize, GEMM_SMEM);
    cudaFuncSetAttribute(gemm_mma<0,1>,
                         cudaFuncAttributeMaxDynamicSharedMemorySize, GEMM_SMEM);
    cudaFuncSetAttribute(gemm_mma<1,1>,
                         cudaFuncAttributeMaxDynamicSharedMemorySize, GEMM_SMEM);

    detect_mask_kernel<<<1, 256>>>((const unsigned char*)mask);

    split_launch(Wqkv, wqh, wql, 3 * D_ * D_);
    split_launch(Wo,   woh, wol, D_ * D_);
    split_launch(W1,   w1h, w1l, FF_ * D_);
    split_launch(W2,   w2h, w2l, D_ * FF_);
    split_launch(x, ah, al, NT * D_);

    // qkv (hi/lo) = x @ Wqkv^T + bqkv
    gemm_mma<0,1><<<dim3(3 * D_ / 128, NT / 128), 256, GEMM_SMEM>>>(
        ah, al, wqh, wql, bqkv, nullptr, qh, ql, NT, 3 * D_, D_);

    // attention -> ctx (hi/lo)
    attn_mma_kernel<<<dim3(S_ / 128, H_, B_), 256, SMEM_ATTN>>>(qh, ql, mask, ch, cl);

    // attn_out = ctx @ Wo^T + bo  (fp32)
    gemm_mma<0,0><<<dim3(D_ / 128, NT / 128), 256, GEMM_SMEM>>>(
        ch, cl, woh, wol, bo, attn, nullptr, nullptr, NT, D_, D_);

    // h = LN1(attn_out + x)  (fp32 + hi/lo)
    ln_residual_kernel<1><<<NT, 256>>>(attn, x, g1, be1, hbuf, hh, hl);

    // f1 (hi/lo) = relu(h @ W1^T + b1)
    gemm_mma<1,1><<<dim3(FF_ / 128, NT / 128), 256, GEMM_SMEM>>>(
        hh, hl, w1h, w1l, b1, nullptr, ah, al, NT, FF_, D_);

    // f2 = f1 @ W2^T + b2  (fp32)
    gemm_mma<0,0><<<dim3(D_ / 128, NT / 128), 256, GEMM_SMEM>>>(
        ah, al, w2h, w2l, b2, f2, nullptr, nullptr, NT, D_, FF_);

    // out = LN2(f2 + h)
    ln_residual_kernel<0><<<NT, 256>>>(f2, hbuf, g2, be2, out, nullptr, nullptr);
}

// round 5
// speedup vs baseline: 3.1801x; 1.4600x over previous
#include <cuda_runtime.h>
#include <cuda_fp16.h>
#include <math.h>
#include <stdint.h>

#define B_   4
#define S_   1024
#define D_   1024
#define H_   16
#define HD_  64
#define FF_  4096
#define NT   (B_*S_)
#define NEGV (-1e9f)

// ---------------- scratch -------------------------------------------------
__device__ float g_attn[NT * D_];
__device__ float g_h   [NT * D_];
__device__ float g_ffn2[NT * D_];
__device__ int   g_mask_mode;

// fp16 operand buffers: B-side (weights, K, V) = exact hi/lo pairs,
// A-side (activations, Q, P) = single fp16.
__device__ __half g_wqkv_h[3*D_*D_], g_wqkv_l[3*D_*D_];
__device__ __half g_wo_h  [D_*D_],   g_wo_l  [D_*D_];
__device__ __half g_w1_h  [FF_*D_],  g_w1_l  [FF_*D_];
__device__ __half g_w2_h  [D_*FF_],  g_w2_l  [D_*FF_];
__device__ __half g_x16  [NT*D_];
__device__ __half g_qkv_h[NT*3*D_],  g_qkv_l[NT*3*D_];
__device__ __half g_ctx16[NT*D_];
__device__ __half g_h16  [NT*D_];
__device__ __half g_f116 [NT*FF_];

// ================= helpers =================================================
__device__ __forceinline__ uint32_t smem_u32(const void* p) {
    uint32_t a;
    asm("{ .reg .u64 t; cvta.to.shared.u64 t, %1; cvt.u32.u64 %0, t; }"
        : "=r"(a) : "l"(p));
    return a;
}
__device__ __forceinline__ void cp16(uint32_t dst, const void* src) {
    asm volatile("cp.async.cg.shared.global [%0], [%1], 16;" :: "r"(dst), "l"(src));
}
#define CP_COMMIT() asm volatile("cp.async.commit_group;" ::: "memory")
#define CP_WAIT0()  asm volatile("cp.async.wait_group 0;" ::: "memory")
#define CP_WAIT1()  asm volatile("cp.async.wait_group 1;" ::: "memory")

#define LDSM4(r0,r1,r2,r3,addr) \
    asm volatile("ldmatrix.sync.aligned.m8n8.x4.shared.b16 {%0,%1,%2,%3}, [%4];" \
        : "=r"(r0), "=r"(r1), "=r"(r2), "=r"(r3) : "r"(addr))
#define LDSM4T(r0,r1,r2,r3,addr) \
    asm volatile("ldmatrix.sync.aligned.m8n8.x4.trans.shared.b16 {%0,%1,%2,%3}, [%4];" \
        : "=r"(r0), "=r"(r1), "=r"(r2), "=r"(r3) : "r"(addr))

__device__ __forceinline__ void mma_f16(
    float& d0, float& d1, float& d2, float& d3,
    uint32_t a0, uint32_t a1, uint32_t a2, uint32_t a3,
    uint32_t b0, uint32_t b1)
{
    asm volatile(
        "mma.sync.aligned.m16n8k16.row.col.f32.f16.f16.f32 "
        "{%0,%1,%2,%3}, {%4,%5,%6,%7}, {%8,%9}, {%0,%1,%2,%3};"
        : "+f"(d0), "+f"(d1), "+f"(d2), "+f"(d3)
        : "r"(a0), "r"(a1), "r"(a2), "r"(a3), "r"(b0), "r"(b1));
}

__device__ __forceinline__ uint32_t pack_h2(float a, float b) {
    __half2 h = __floats2half2_rn(a, b);
    return *(uint32_t*)&h;
}
__device__ __forceinline__ void split_pack_h(float a, float b,
                                             uint32_t& hi, uint32_t& lo) {
    __half ha = __float2half_rn(a), hb = __float2half_rn(b);
    float  ra = a - __half2float(ha), rb = b - __half2float(hb);
    __half2 H = __halves2half2(ha, hb);
    __half2 L = __floats2half2_rn(ra, rb);
    hi = *(uint32_t*)&H; lo = *(uint32_t*)&L;
}

// ---------------- split kernels --------------------------------------------
__global__ void __launch_bounds__(256) split_w_kernel(
    const float* __restrict__ in, __half* __restrict__ hi,
    __half* __restrict__ lo, int n)
{
    int i = (blockIdx.x * 256 + threadIdx.x) * 4;
    if (i >= n) return;
    float4 v = *(const float4*)(in + i);
    uint32_t h0, l0, h1, l1;
    split_pack_h(v.x, v.y, h0, l0);
    split_pack_h(v.z, v.w, h1, l1);
    *(uint32_t*)(hi + i)     = h0;  *(uint32_t*)(hi + i + 2) = h1;
    *(uint32_t*)(lo + i)     = l0;  *(uint32_t*)(lo + i + 2) = l1;
}

__global__ void __launch_bounds__(256) cvt_h_kernel(
    const float* __restrict__ in, __half* __restrict__ o16, int n)
{
    int i = (blockIdx.x * 256 + threadIdx.x) * 4;
    if (i >= n) return;
    float4 v = *(const float4*)(in + i);
    *(uint32_t*)(o16 + i)     = pack_h2(v.x, v.y);
    *(uint32_t*)(o16 + i + 2) = pack_h2(v.z, v.w);
}

// ---------------- HMMA fp16 2-pass GEMM: C = A * B^T + bias ----------------
// A single fp16, B = (Bh + Bl) exact pair. 128x128 tile, BK=32, 256 thr.
#define TSTRIDE   80
#define TMAT      (128 * TSTRIDE)
#define TSTAGE    (3 * TMAT)
#define GEMM_SMEM (2 * TSTAGE)

// OUT: 0 = fp32 C; 1 = fp16 single Ch; 2 = fp16 pair Ch,Cl
template<int RELU, int OUT>
__global__ void __launch_bounds__(256, 1) gemm_mma(
    const __half* __restrict__ A,
    const __half* __restrict__ Bh, const __half* __restrict__ Bl,
    const float* __restrict__ bias, float* __restrict__ C,
    __half* __restrict__ Ch, __half* __restrict__ Cl,
    int M, int N, int K)
{
    extern __shared__ char smem[];
    const uint32_t sbase = smem_u32(smem);
    const int tid  = threadIdx.x;
    const int wid  = tid >> 5;
    const int lane = tid & 31;
    const int row0 = blockIdx.y * 128;
    const int col0 = blockIdx.x * 128;
    const int wm   = wid & 1;
    const int wn   = wid >> 1;

    const __half* gsrc[3] = {
        A + (size_t)row0 * K, Bh + (size_t)col0 * K, Bl + (size_t)col0 * K };

    const int l_mat = lane >> 3, l_r = lane & 7;
    const int frag_row = l_r + (l_mat & 1) * 8;
    const int frag_kb  = (l_mat >> 1) * 16;

    const int cp_row = tid >> 2;
    const int cp_c   = tid & 3;

    float acc[4][4][4];
    #pragma unroll
    for (int i = 0; i < 4; i++)
        #pragma unroll
        for (int j = 0; j < 4; j++)
            #pragma unroll
            for (int r = 0; r < 4; r++) acc[i][j][r] = 0.f;

    const int nstage = K >> 5;

    {
        #pragma unroll
        for (int m = 0; m < 3; m++) {
            const uint32_t mbuf = sbase + m * TMAT;
            const __half* g = gsrc[m] + cp_c * 8;
            #pragma unroll
            for (int p = 0; p < 2; p++) {
                int r = cp_row + p * 64;
                cp16(mbuf + r * TSTRIDE + cp_c * 16, g + (size_t)r * K);
            }
        }
        CP_COMMIT();
    }

    for (int s = 0; s < nstage; s++) {
        CP_WAIT0();
        __syncthreads();

        if (s + 1 < nstage) {
            const int k0 = (s + 1) << 5;
            const uint32_t bufb = sbase + ((s + 1) & 1) * TSTAGE;
            #pragma unroll
            for (int m = 0; m < 3; m++) {
                const uint32_t mbuf = bufb + m * TMAT;
                const __half* g = gsrc[m] + k0 + cp_c * 8;
                #pragma unroll
                for (int p = 0; p < 2; p++) {
                    int r = cp_row + p * 64;
                    cp16(mbuf + r * TSTRIDE + cp_c * 16, g + (size_t)r * K);
                }
            }
            CP_COMMIT();
        }

        const uint32_t buf = sbase + (s & 1) * TSTAGE;
        const uint32_t bA  = buf;
        const uint32_t bBh = buf + TMAT;
        const uint32_t bBl = buf + 2 * TMAT;

        #pragma unroll
        for (int ks = 0; ks < 2; ks++) {
            const int kb = ks * 32 + frag_kb;

            uint32_t a[4][4], bh[2][4], bl[2][4];
            #pragma unroll
            for (int mi = 0; mi < 4; mi++) {
                uint32_t ra = (wm * 64 + mi * 16 + frag_row) * TSTRIDE + kb;
                LDSM4(a[mi][0], a[mi][1], a[mi][2], a[mi][3], bA + ra);
            }
            #pragma unroll
            for (int nb = 0; nb < 2; nb++) {
                uint32_t rb = (wn * 32 + nb * 16 + frag_row) * TSTRIDE + kb;
                LDSM4(bh[nb][0], bh[nb][1], bh[nb][2], bh[nb][3], bBh + rb);
                LDSM4(bl[nb][0], bl[nb][1], bl[nb][2], bl[nb][3], bBl + rb);
            }

            #pragma unroll
            for (int mi = 0; mi < 4; mi++)
                #pragma unroll
                for (int ni = 0; ni < 4; ni++) {
                    const int nb = ni >> 1, no = ni & 1;
                    mma_f16(acc[mi][ni][0], acc[mi][ni][1],
                            acc[mi][ni][2], acc[mi][ni][3],
                            a[mi][0], a[mi][1], a[mi][2], a[mi][3],
                            bh[nb][no], bh[nb][no + 2]);
                    mma_f16(acc[mi][ni][0], acc[mi][ni][1],
                            acc[mi][ni][2], acc[mi][ni][3],
                            a[mi][0], a[mi][1], a[mi][2], a[mi][3],
                            bl[nb][no], bl[nb][no + 2]);
                }
        }
        __syncthreads();
    }

    const int g8  = lane >> 2;
    const int tig = lane & 3;
    #pragma unroll
    for (int mi = 0; mi < 4; mi++) {
        #pragma unroll
        for (int ni = 0; ni < 4; ni++) {
            int col = col0 + wn * 32 + ni * 8 + tig * 2;
            float2 bs = *(const float2*)(bias + col);
            int r0 = row0 + wm * 64 + mi * 16 + g8;
            float2 v0 = { acc[mi][ni][0] + bs.x, acc[mi][ni][1] + bs.y };
            float2 v1 = { acc[mi][ni][2] + bs.x, acc[mi][ni][3] + bs.y };
            if (RELU) {
                v0.x = fmaxf(v0.x, 0.f); v0.y = fmaxf(v0.y, 0.f);
                v1.x = fmaxf(v1.x, 0.f); v1.y = fmaxf(v1.y, 0.f);
            }
            if (OUT == 0) {
                *(float2*)(C + (size_t)r0 * N + col)       = v0;
                *(float2*)(C + (size_t)(r0 + 8) * N + col) = v1;
            } else if (OUT == 1) {
                *(uint32_t*)(Ch + (size_t)r0 * N + col)       = pack_h2(v0.x, v0.y);
                *(uint32_t*)(Ch + (size_t)(r0 + 8) * N + col) = pack_h2(v1.x, v1.y);
            } else {
                uint32_t h0, l0, h1, l1;
                split_pack_h(v0.x, v0.y, h0, l0);
                split_pack_h(v1.x, v1.y, h1, l1);
                *(uint32_t*)(Ch + (size_t)r0 * N + col)       = h0;
                *(uint32_t*)(Cl + (size_t)r0 * N + col)       = l0;
                *(uint32_t*)(Ch + (size_t)(r0 + 8) * N + col) = h1;
                *(uint32_t*)(Cl + (size_t)(r0 + 8) * N + col) = l1;
            }
        }
    }
}

// ---------------- mask dtype probe ----------------------------------------
__global__ void detect_mask_kernel(const unsigned char* __restrict__ m) {
    __shared__ int f3f, foff;
    if (threadIdx.x == 0) { f3f = 0; foff = 0; }
    __syncthreads();
    int l3f = 0, loff = 0;
    for (int i = threadIdx.x; i < 65536; i += blockDim.x) {
        unsigned char v = m[i];
        if (v == 0x3f) l3f = 1;
        else if (v && (i & 3)) loff = 1;
    }
    if (l3f)  atomicOr(&f3f, 1);
    if (loff) atomicOr(&foff, 1);
    __syncthreads();
    if (threadIdx.x == 0) g_mask_mode = f3f ? 2 : (foff ? 1 : 0);
}

__device__ __forceinline__ float mask_val(const void* mp, int idx) {
    int mode = g_mask_mode;
    if (mode == 0) return ((const int*)mp)[idx] ? 1.f : 0.f;
    if (mode == 1) return ((const unsigned char*)mp)[idx] ? 1.f : 0.f;
    return ((const float*)mp)[idx];
}

// ---------------- tensor-core flash attention (fp16 2-pass) ----------------
// Br=128 (8 warps x 16 rows), Bc=64. Q single fp16, K/V exact hi/lo pairs.
#define ASTRIDE 144
#define KVMAT   (64 * ASTRIDE)
#define KVSTAGE (4 * KVMAT)
#define SMEM_ATTN (128 * ASTRIDE + 2 * KVSTAGE + S_ * 4)

__device__ __forceinline__ void kv_prefetch(
    uint32_t sKV, int stg, int jb, int tid, int rowbase, int h,
    const __half* QKVh, const __half* QKVl)
{
    const uint32_t base = sKV + stg * KVSTAGE;
    const int r  = tid >> 2;
    const int c0 = tid & 3;
    const size_t go = (size_t)(rowbase + jb * 64 + r) * (3 * D_) + h * HD_;
    const __half* srcs[4] = {
        QKVh + go + D_, QKVl + go + D_, QKVh + go + 2 * D_, QKVl + go + 2 * D_ };
    #pragma unroll
    for (int m = 0; m < 4; m++) {
        const uint32_t mb = base + m * KVMAT + r * ASTRIDE;
        cp16(mb + c0 * 16,       srcs[m] + c0 * 8);
        cp16(mb + (c0 + 4) * 16, srcs[m] + (c0 + 4) * 8);
    }
}

__global__ void __launch_bounds__(256, 1) attn_mma_kernel(
    const __half* __restrict__ QKVh, const __half* __restrict__ QKVl,
    const void* __restrict__ mask, __half* __restrict__ Cc)
{
    const int it = blockIdx.x, h = blockIdx.y, b = blockIdx.z;
    extern __shared__ char sm8[];
    const uint32_t sb = smem_u32(sm8);
    const uint32_t sQ  = sb;
    const uint32_t sKV = sb + 128 * ASTRIDE;
    float* mk = (float*)(sm8 + 128 * ASTRIDE + 2 * KVSTAGE);

    const int tid = threadIdx.x, w = tid >> 5, lane = tid & 31;
    const int i0 = it * 128, rowbase = b * S_;
    const int frag_row = (lane & 7) + ((lane >> 3) & 1) * 8;
    const int frag_kb  = (lane >> 4) * 16;
    const float scale = 0.125f;

    // Q tile (128 rows x 64 fp16, single precision level)
    {
        int r = tid >> 1;
        const size_t go = (size_t)(rowbase + i0 + r) * (3 * D_) + h * HD_;
        #pragma unroll
        for (int c = 0; c < 4; c++) {
            int ch = (tid & 1) * 4 + c;
            cp16(sQ + r * ASTRIDE + ch * 16, QKVh + go + ch * 8);
        }
    }
    for (int i = tid; i < S_; i += 256)
        mk[i] = mask_val(mask, (b * H_ + h) * S_ + i);

    kv_prefetch(sKV, 0, 0, tid, rowbase, h, QKVh, QKVl);
    CP_COMMIT();
    CP_WAIT0();
    __syncthreads();

    uint32_t q[4][4];
    #pragma unroll
    for (int kk = 0; kk < 4; kk++) {
        uint32_t a = (w * 16 + frag_row) * ASTRIDE + kk * 32 + frag_kb;
        LDSM4(q[kk][0], q[kk][1], q[kk][2], q[kk][3], sQ + a);
    }

    float m_run[2] = { -3.0e38f, -3.0e38f };
    float l_run[2] = { 0.f, 0.f };
    float o[8][4];
    #pragma unroll
    for (int d = 0; d < 8; d++)
        #pragma unroll
        for (int r = 0; r < 4; r++) o[d][r] = 0.f;

    for (int jb = 0; jb < S_ / 64; jb++) {
        if (jb + 1 < S_ / 64) {
            kv_prefetch(sKV, (jb + 1) & 1, jb + 1, tid, rowbase, h, QKVh, QKVl);
            CP_COMMIT();
            CP_WAIT1();
        } else {
            CP_WAIT0();
        }
        __syncthreads();

        const uint32_t kvb = sKV + (jb & 1) * KVSTAGE;
        const uint32_t bKH = kvb, bKL = kvb + KVMAT;
        const uint32_t bVH = kvb + 2 * KVMAT, bVL = kvb + 3 * KVMAT;

        // ---- S = Q K^T (2-pass) ----
        float s[8][4];
        #pragma unroll
        for (int t = 0; t < 8; t++)
            #pragma unroll
            for (int r = 0; r < 4; r++) s[t][r] = 0.f;

        #pragma unroll
        for (int kk = 0; kk < 4; kk++) {
            #pragma unroll
            for (int nb = 0; nb < 4; nb++) {
                uint32_t kh0, kh1, kh2, kh3, kl0, kl1, kl2, kl3;
                uint32_t ad = (nb * 16 + frag_row) * ASTRIDE + kk * 32 + frag_kb;
                LDSM4(kh0, kh1, kh2, kh3, bKH + ad);
                LDSM4(kl0, kl1, kl2, kl3, bKL + ad);
                const int t0 = nb * 2, t1 = nb * 2 + 1;
                mma_f16(s[t0][0], s[t0][1], s[t0][2], s[t0][3],
                        q[kk][0], q[kk][1], q[kk][2], q[kk][3], kh0, kh2);
                mma_f16(s[t0][0], s[t0][1], s[t0][2], s[t0][3],
                        q[kk][0], q[kk][1], q[kk][2], q[kk][3], kl0, kl2);
                mma_f16(s[t1][0], s[t1][1], s[t1][2], s[t1][3],
                        q[kk][0], q[kk][1], q[kk][2], q[kk][3], kh1, kh3);
                mma_f16(s[t1][0], s[t1][1], s[t1][2], s[t1][3],
                        q[kk][0], q[kk][1], q[kk][2], q[kk][3], kl1, kl3);
            }
        }

        // ---- mask + scale ----
        #pragma unroll
        for (int t = 0; t < 8; t++) {
            float mv0 = mk[jb * 64 + t * 8 + (lane & 3) * 2];
            float mv1 = mk[jb * 64 + t * 8 + (lane & 3) * 2 + 1];
            s[t][0] = (mv0 > 0.5f) ? s[t][0] * scale : NEGV;
            s[t][1] = (mv1 > 0.5f) ? s[t][1] * scale : NEGV;
            s[t][2] = (mv0 > 0.5f) ? s[t][2] * scale : NEGV;
            s[t][3] = (mv1 > 0.5f) ? s[t][3] * scale : NEGV;
        }

        // ---- online softmax ----
        float mx0 = -3.0e38f, mx1 = -3.0e38f;
        #pragma unroll
        for (int t = 0; t < 8; t++) {
            mx0 = fmaxf(mx0, fmaxf(s[t][0], s[t][1]));
            mx1 = fmaxf(mx1, fmaxf(s[t][2], s[t][3]));
        }
        mx0 = fmaxf(mx0, __shfl_xor_sync(0xffffffffu, mx0, 1));
        mx0 = fmaxf(mx0, __shfl_xor_sync(0xffffffffu, mx0, 2));
        mx1 = fmaxf(mx1, __shfl_xor_sync(0xffffffffu, mx1, 1));
        mx1 = fmaxf(mx1, __shfl_xor_sync(0xffffffffu, mx1, 2));
        float nm0 = fmaxf(m_run[0], mx0), nm1 = fmaxf(m_run[1], mx1);
        float corr0 = __expf(m_run[0] - nm0), corr1 = __expf(m_run[1] - nm1);
        m_run[0] = nm0; m_run[1] = nm1;

        float sum0 = 0.f, sum1 = 0.f;
        #pragma unroll
        for (int t = 0; t < 8; t++) {
            s[t][0] = __expf(s[t][0] - nm0); sum0 += s[t][0];
            s[t][1] = __expf(s[t][1] - nm0); sum0 += s[t][1];
            s[t][2] = __expf(s[t][2] - nm1); sum1 += s[t][2];
            s[t][3] = __expf(s[t][3] - nm1); sum1 += s[t][3];
        }
        sum0 += __shfl_xor_sync(0xffffffffu, sum0, 1);
        sum0 += __shfl_xor_sync(0xffffffffu, sum0, 2);
        sum1 += __shfl_xor_sync(0xffffffffu, sum1, 1);
        sum1 += __shfl_xor_sync(0xffffffffu, sum1, 2);
        l_run[0] = l_run[0] * corr0 + sum0;
        l_run[1] = l_run[1] * corr1 + sum1;

        #pragma unroll
        for (int d = 0; d < 8; d++) {
            o[d][0] *= corr0; o[d][1] *= corr0;
            o[d][2] *= corr1; o[d][3] *= corr1;
        }

        // ---- O += P V (P single fp16, V exact pair) ----
        #pragma unroll
        for (int kk = 0; kk < 4; kk++) {
            const int t0 = kk * 2, t1 = kk * 2 + 1;
            uint32_t pa[4];
            pa[0] = pack_h2(s[t0][0], s[t0][1]);
            pa[1] = pack_h2(s[t0][2], s[t0][3]);
            pa[2] = pack_h2(s[t1][0], s[t1][1]);
            pa[3] = pack_h2(s[t1][2], s[t1][3]);

            const uint32_t vrow =
                (kk * 16 + ((lane >> 3) & 1) * 8 + (lane & 7)) * ASTRIDE +
                (lane >> 4) * 16;
            #pragma unroll
            for (int qd = 0; qd < 4; qd++) {
                uint32_t vh0, vh1, vh2, vh3, vl0, vl1, vl2, vl3;
                LDSM4T(vh0, vh1, vh2, vh3, bVH + vrow + qd * 32);
                LDSM4T(vl0, vl1, vl2, vl3, bVL + vrow + qd * 32);
                const int d0 = qd * 2, d1 = qd * 2 + 1;
                mma_f16(o[d0][0], o[d0][1], o[d0][2], o[d0][3],
                        pa[0], pa[1], pa[2], pa[3], vh0, vh1);
                mma_f16(o[d0][0], o[d0][1], o[d0][2], o[d0][3],
                        pa[0], pa[1], pa[2], pa[3], vl0, vl1);
                mma_f16(o[d1][0], o[d1][1], o[d1][2], o[d1][3],
                        pa[0], pa[1], pa[2], pa[3], vh2, vh3);
                mma_f16(o[d1][0], o[d1][1], o[d1][2], o[d1][3],
                        pa[0], pa[1], pa[2], pa[3], vl2, vl3);
            }
        }
        __syncthreads();
    }

    // ---- epilogue: ctx single fp16 ----
    const float inv0 = 1.f / l_run[0], inv1 = 1.f / l_run[1];
    const int tok0 = rowbase + i0 + w * 16 + (lane >> 2);
    #pragma unroll
    for (int d = 0; d < 8; d++) {
        int col = h * HD_ + d * 8 + (lane & 3) * 2;
        *(uint32_t*)(Cc + (size_t)tok0 * D_ + col) =
            pack_h2(o[d][0] * inv0, o[d][1] * inv0);
        *(uint32_t*)(Cc + (size_t)(tok0 + 8) * D_ + col) =
            pack_h2(o[d][2] * inv1, o[d][3] * inv1);
    }
}

// ---------------- residual + LayerNorm -------------------------------------
template<int SPLIT>
__global__ void __launch_bounds__(256) ln_residual_kernel(
    const float* __restrict__ a, const float* __restrict__ res,
    const float* __restrict__ gamma, const float* __restrict__ beta,
    float* __restrict__ out, __half* __restrict__ oh)
{
    const int row = blockIdx.x;
    const int tid = threadIdx.x;
    const float* pa = a   + (size_t)row * D_;
    const float* pr = res + (size_t)row * D_;

    float v[4], sum = 0.f, sq = 0.f;
    #pragma unroll
    for (int i = 0; i < 4; i++) {
        int c = tid + i * 256;
        float t = pa[c] + pr[c];
        v[i] = t; sum += t; sq += t * t;
    }
    #pragma unroll
    for (int o2 = 16; o2; o2 >>= 1) {
        sum += __shfl_xor_sync(0xffffffffu, sum, o2);
        sq  += __shfl_xor_sync(0xffffffffu, sq,  o2);
    }
    __shared__ float sh1[8], sh2[8];
    __shared__ float smean, srstd;
    if ((tid & 31) == 0) { sh1[tid >> 5] = sum; sh2[tid >> 5] = sq; }
    __syncthreads();
    if (tid == 0) {
        float s = 0.f, s2 = 0.f;
        #pragma unroll
        for (int i = 0; i < 8; i++) { s += sh1[i]; s2 += sh2[i]; }
        float mean = s * (1.f / D_);
        float var  = s2 * (1.f / D_) - mean * mean;
        smean = mean;
        srstd = rsqrtf(var + 1e-12f);
    }
    __syncthreads();
    float mean = smean, rstd = srstd;
    #pragma unroll
    for (int i = 0; i < 4; i++) {
        int c = tid + i * 256;
        float r = gamma[c] * (v[i] - mean) * rstd + beta[c];
        out[(size_t)row * D_ + c] = r;
        if (SPLIT) oh[(size_t)row * D_ + c] = __float2half_rn(r);
    }
}

// ---------------- launch ---------------------------------------------------
extern "C" void kernel_launch(void* const* d_in, const int* in_sizes, int n_in,
                              void* d_out, int out_size)
{
    const float* x    = (const float*)d_in[0];
    const void*  mask = d_in[1];
    const float* Wqkv = (const float*)d_in[2];
    const float* bqkv = (const float*)d_in[3];
    const float* Wo   = (const float*)d_in[4];
    const float* bo   = (const float*)d_in[5];
    const float* W1   = (const float*)d_in[6];
    const float* b1   = (const float*)d_in[7];
    const float* W2   = (const float*)d_in[8];
    const float* b2   = (const float*)d_in[9];
    const float* g1   = (const float*)d_in[10];
    const float* be1  = (const float*)d_in[11];
    const float* g2   = (const float*)d_in[12];
    const float* be2  = (const float*)d_in[13];
    float* out = (float*)d_out;

    float *attn, *hbuf, *f2;
    cudaGetSymbolAddress((void**)&attn, g_attn);
    cudaGetSymbolAddress((void**)&hbuf, g_h);
    cudaGetSymbolAddress((void**)&f2,   g_ffn2);

    __half *wqh, *wql, *woh, *wol, *w1h, *w1l, *w2h, *w2l;
    __half *x16, *qh, *ql, *ctx16, *h16, *f116;
    cudaGetSymbolAddress((void**)&wqh, g_wqkv_h); cudaGetSymbolAddress((void**)&wql, g_wqkv_l);
    cudaGetSymbolAddress((void**)&woh, g_wo_h);   cudaGetSymbolAddress((void**)&wol, g_wo_l);
    cudaGetSymbolAddress((void**)&w1h, g_w1_h);   cudaGetSymbolAddress((void**)&w1l, g_w1_l);
    cudaGetSymbolAddress((void**)&w2h, g_w2_h);   cudaGetSymbolAddress((void**)&w2l, g_w2_l);
    cudaGetSymbolAddress((void**)&x16, g_x16);
    cudaGetSymbolAddress((void**)&qh,  g_qkv_h);  cudaGetSymbolAddress((void**)&ql,  g_qkv_l);
    cudaGetSymbolAddress((void**)&ctx16, g_ctx16);
    cudaGetSymbolAddress((void**)&h16, g_h16);
    cudaGetSymbolAddress((void**)&f116, g_f116);

    cudaFuncSetAttribute(attn_mma_kernel,
                         cudaFuncAttributeMaxDynamicSharedMemorySize, SMEM_ATTN);
    cudaFuncSetAttribute(gemm_mma<0,0>,
                         cudaFuncAttributeMaxDynamicSharedMemorySize, GEMM_SMEM);
    cudaFuncSetAttribute(gemm_mma<0,1>,
                         cudaFuncAttributeMaxDynamicSharedMemorySize, GEMM_SMEM);
    cudaFuncSetAttribute(gemm_mma<0,2>,
                         cudaFuncAttributeMaxDynamicSharedMemorySize, GEMM_SMEM);
    cudaFuncSetAttribute(gemm_mma<1,1>,
                         cudaFuncAttributeMaxDynamicSharedMemorySize, GEMM_SMEM);

    detect_mask_kernel<<<1, 256>>>((const unsigned char*)mask);

    split_w_kernel<<<(3*D_*D_/4 + 255)/256, 256>>>(Wqkv, wqh, wql, 3*D_*D_);
    split_w_kernel<<<(D_*D_/4 + 255)/256, 256>>>(Wo, woh, wol, D_*D_);
    split_w_kernel<<<(FF_*D_/4 + 255)/256, 256>>>(W1, w1h, w1l, FF_*D_);
    split_w_kernel<<<(D_*FF_/4 + 255)/256, 256>>>(W2, w2h, w2l, D_*FF_);
    cvt_h_kernel<<<(NT*D_/4 + 255)/256, 256>>>(x, x16, NT*D_);

    // qkv = x @ Wqkv^T + bqkv -> fp16 hi/lo (K,V need exact pairs; Q uses hi)
    gemm_mma<0,2><<<dim3(3 * D_ / 128, NT / 128), 256, GEMM_SMEM>>>(
        x16, wqh, wql, bqkv, nullptr, qh, ql, NT, 3 * D_, D_);

    // attention -> ctx fp16
    attn_mma_kernel<<<dim3(S_ / 128, H_, B_), 256, SMEM_ATTN>>>(qh, ql, mask, ctx16);

    // attn_out = ctx @ Wo^T + bo (fp32)
    gemm_mma<0,0><<<dim3(D_ / 128, NT / 128), 256, GEMM_SMEM>>>(
        ctx16, woh, wol, bo, attn, nullptr, nullptr, NT, D_, D_);

    // h = LN1(attn_out + x) (fp32 + fp16)
    ln_residual_kernel<1><<<NT, 256>>>(attn, x, g1, be1, hbuf, h16);

    // f1 = relu(h @ W1^T + b1) -> fp16
    gemm_mma<1,1><<<dim3(FF_ / 128, NT / 128), 256, GEMM_SMEM>>>(
        h16, w1h, w1l, b1, nullptr, f116, nullptr, NT, FF_, D_);

    // f2 = f1 @ W2^T + b2 (fp32)
    gemm_mma<0,0><<<dim3(D_ / 128, NT / 128), 256, GEMM_SMEM>>>(
        f116, w2h, w2l, b2, f2, nullptr, nullptr, NT, D_, FF_);

    // out = LN2(f2 + h)
    ln_residual_kernel<0><<<NT, 256>>>(f2, hbuf, g2, be2, out, nullptr);
}

// round 6
// speedup vs baseline: 5.4157x; 1.7030x over previous
#include <cuda_runtime.h>
#include <cuda_fp16.h>
#include <math.h>
#include <stdint.h>

#define B_   4
#define S_   1024
#define D_   1024
#define H_   16
#define HD_  64
#define FF_  4096
#define NT   (B_*S_)
#define NEGV (-1e9f)

// ---------------- scratch -------------------------------------------------
__device__ float g_attn[NT * D_];
__device__ float g_h   [NT * D_];
__device__ float g_ffn2[NT * D_];
__device__ int   g_mask_mode;

__device__ __half g_wqkv16[3*D_*D_];
__device__ __half g_wo16  [D_*D_];
__device__ __half g_w116  [FF_*D_];
__device__ __half g_w216  [D_*FF_];
__device__ __half g_x16   [NT*D_];
__device__ __half g_qkv16 [NT*3*D_];
__device__ __half g_ctx16 [NT*D_];
__device__ __half g_h16   [NT*D_];
__device__ __half g_f116  [NT*FF_];

// ================= helpers =================================================
__device__ __forceinline__ uint32_t smem_u32(const void* p) {
    uint32_t a;
    asm("{ .reg .u64 t; cvta.to.shared.u64 t, %1; cvt.u32.u64 %0, t; }"
        : "=r"(a) : "l"(p));
    return a;
}
__device__ __forceinline__ void cp16(uint32_t dst, const void* src) {
    asm volatile("cp.async.cg.shared.global [%0], [%1], 16;" :: "r"(dst), "l"(src));
}
#define CP_COMMIT() asm volatile("cp.async.commit_group;" ::: "memory")
#define CP_WAIT0()  asm volatile("cp.async.wait_group 0;" ::: "memory")
#define CP_WAIT1()  asm volatile("cp.async.wait_group 1;" ::: "memory")

#define LDSM4(r0,r1,r2,r3,addr) \
    asm volatile("ldmatrix.sync.aligned.m8n8.x4.shared.b16 {%0,%1,%2,%3}, [%4];" \
        : "=r"(r0), "=r"(r1), "=r"(r2), "=r"(r3) : "r"(addr))
#define LDSM4T(r0,r1,r2,r3,addr) \
    asm volatile("ldmatrix.sync.aligned.m8n8.x4.trans.shared.b16 {%0,%1,%2,%3}, [%4];" \
        : "=r"(r0), "=r"(r1), "=r"(r2), "=r"(r3) : "r"(addr))

__device__ __forceinline__ void mma_f16(
    float& d0, float& d1, float& d2, float& d3,
    uint32_t a0, uint32_t a1, uint32_t a2, uint32_t a3,
    uint32_t b0, uint32_t b1)
{
    asm volatile(
        "mma.sync.aligned.m16n8k16.row.col.f32.f16.f16.f32 "
        "{%0,%1,%2,%3}, {%4,%5,%6,%7}, {%8,%9}, {%0,%1,%2,%3};"
        : "+f"(d0), "+f"(d1), "+f"(d2), "+f"(d3)
        : "r"(a0), "r"(a1), "r"(a2), "r"(a3), "r"(b0), "r"(b1));
}

__device__ __forceinline__ uint32_t pack_h2(float a, float b) {
    __half2 h = __floats2half2_rn(a, b);
    return *(uint32_t*)&h;
}

// ---------------- fp32 -> fp16 convert -------------------------------------
__global__ void __launch_bounds__(256) cvt_h_kernel(
    const float* __restrict__ in, __half* __restrict__ o16, int n)
{
    int i = (blockIdx.x * 256 + threadIdx.x) * 4;
    if (i >= n) return;
    float4 v = *(const float4*)(in + i);
    *(uint32_t*)(o16 + i)     = pack_h2(v.x, v.y);
    *(uint32_t*)(o16 + i + 2) = pack_h2(v.z, v.w);
}

// ---------------- HMMA fp16 single-pass GEMM: C = A * B^T + bias -----------
// 128x128 tile, BK=32, 256 threads (8 warps of 64x32).
#define TSTRIDE   80
#define TMAT      (128 * TSTRIDE)
#define TSTAGE    (2 * TMAT)
#define GEMM_SMEM (2 * TSTAGE)

// OUT: 0 = fp32 C; 1 = fp16 Ch
template<int RELU, int OUT>
__global__ void __launch_bounds__(256, 1) gemm_mma(
    const __half* __restrict__ A, const __half* __restrict__ Bm,
    const float* __restrict__ bias, float* __restrict__ C,
    __half* __restrict__ Ch,
    int M, int N, int K)
{
    extern __shared__ char smem[];
    const uint32_t sbase = smem_u32(smem);
    const int tid  = threadIdx.x;
    const int wid  = tid >> 5;
    const int lane = tid & 31;
    const int row0 = blockIdx.y * 128;
    const int col0 = blockIdx.x * 128;
    const int wm   = wid & 1;
    const int wn   = wid >> 1;

    const __half* gsrc[2] = { A + (size_t)row0 * K, Bm + (size_t)col0 * K };

    const int l_mat = lane >> 3, l_r = lane & 7;
    const int frag_row = l_r + (l_mat & 1) * 8;
    const int frag_kb  = (l_mat >> 1) * 16;

    const int cp_row = tid >> 2;
    const int cp_c   = tid & 3;

    float acc[4][4][4];
    #pragma unroll
    for (int i = 0; i < 4; i++)
        #pragma unroll
        for (int j = 0; j < 4; j++)
            #pragma unroll
            for (int r = 0; r < 4; r++) acc[i][j][r] = 0.f;

    const int nstage = K >> 5;

    {
        #pragma unroll
        for (int m = 0; m < 2; m++) {
            const uint32_t mbuf = sbase + m * TMAT;
            const __half* g = gsrc[m] + cp_c * 8;
            #pragma unroll
            for (int p = 0; p < 2; p++) {
                int r = cp_row + p * 64;
                cp16(mbuf + r * TSTRIDE + cp_c * 16, g + (size_t)r * K);
            }
        }
        CP_COMMIT();
    }

    for (int s = 0; s < nstage; s++) {
        CP_WAIT0();
        __syncthreads();

        if (s + 1 < nstage) {
            const int k0 = (s + 1) << 5;
            const uint32_t bufb = sbase + ((s + 1) & 1) * TSTAGE;
            #pragma unroll
            for (int m = 0; m < 2; m++) {
                const uint32_t mbuf = bufb + m * TMAT;
                const __half* g = gsrc[m] + k0 + cp_c * 8;
                #pragma unroll
                for (int p = 0; p < 2; p++) {
                    int r = cp_row + p * 64;
                    cp16(mbuf + r * TSTRIDE + cp_c * 16, g + (size_t)r * K);
                }
            }
            CP_COMMIT();
        }

        const uint32_t buf = sbase + (s & 1) * TSTAGE;
        const uint32_t bA = buf;
        const uint32_t bB = buf + TMAT;

        #pragma unroll
        for (int ks = 0; ks < 2; ks++) {
            const int kb = ks * 32 + frag_kb;

            uint32_t a[4][4], b[2][4];
            #pragma unroll
            for (int mi = 0; mi < 4; mi++) {
                uint32_t ra = (wm * 64 + mi * 16 + frag_row) * TSTRIDE + kb;
                LDSM4(a[mi][0], a[mi][1], a[mi][2], a[mi][3], bA + ra);
            }
            #pragma unroll
            for (int nb = 0; nb < 2; nb++) {
                uint32_t rb = (wn * 32 + nb * 16 + frag_row) * TSTRIDE + kb;
                LDSM4(b[nb][0], b[nb][1], b[nb][2], b[nb][3], bB + rb);
            }

            #pragma unroll
            for (int mi = 0; mi < 4; mi++)
                #pragma unroll
                for (int ni = 0; ni < 4; ni++) {
                    const int nb = ni >> 1, no = ni & 1;
                    mma_f16(acc[mi][ni][0], acc[mi][ni][1],
                            acc[mi][ni][2], acc[mi][ni][3],
                            a[mi][0], a[mi][1], a[mi][2], a[mi][3],
                            b[nb][no], b[nb][no + 2]);
                }
        }
        __syncthreads();
    }

    const int g8  = lane >> 2;
    const int tig = lane & 3;
    #pragma unroll
    for (int mi = 0; mi < 4; mi++) {
        #pragma unroll
        for (int ni = 0; ni < 4; ni++) {
            int col = col0 + wn * 32 + ni * 8 + tig * 2;
            float2 bs = *(const float2*)(bias + col);
            int r0 = row0 + wm * 64 + mi * 16 + g8;
            float2 v0 = { acc[mi][ni][0] + bs.x, acc[mi][ni][1] + bs.y };
            float2 v1 = { acc[mi][ni][2] + bs.x, acc[mi][ni][3] + bs.y };
            if (RELU) {
                v0.x = fmaxf(v0.x, 0.f); v0.y = fmaxf(v0.y, 0.f);
                v1.x = fmaxf(v1.x, 0.f); v1.y = fmaxf(v1.y, 0.f);
            }
            if (OUT == 0) {
                *(float2*)(C + (size_t)r0 * N + col)       = v0;
                *(float2*)(C + (size_t)(r0 + 8) * N + col) = v1;
            } else {
                *(uint32_t*)(Ch + (size_t)r0 * N + col)       = pack_h2(v0.x, v0.y);
                *(uint32_t*)(Ch + (size_t)(r0 + 8) * N + col) = pack_h2(v1.x, v1.y);
            }
        }
    }
}

// ---------------- mask dtype probe ----------------------------------------
__global__ void detect_mask_kernel(const unsigned char* __restrict__ m) {
    __shared__ int f3f, foff;
    if (threadIdx.x == 0) { f3f = 0; foff = 0; }
    __syncthreads();
    int l3f = 0, loff = 0;
    for (int i = threadIdx.x; i < 65536; i += blockDim.x) {
        unsigned char v = m[i];
        if (v == 0x3f) l3f = 1;
        else if (v && (i & 3)) loff = 1;
    }
    if (l3f)  atomicOr(&f3f, 1);
    if (loff) atomicOr(&foff, 1);
    __syncthreads();
    if (threadIdx.x == 0) g_mask_mode = f3f ? 2 : (foff ? 1 : 0);
}

__device__ __forceinline__ float mask_val(const void* mp, int idx) {
    int mode = g_mask_mode;
    if (mode == 0) return ((const int*)mp)[idx] ? 1.f : 0.f;
    if (mode == 1) return ((const unsigned char*)mp)[idx] ? 1.f : 0.f;
    return ((const float*)mp)[idx];
}

// ---------------- tensor-core flash attention (fp16 1-pass) ----------------
// Br=128 (8 warps x 16 rows), Bc=64.
#define ASTRIDE 144
#define KVMAT   (64 * ASTRIDE)
#define KVSTAGE (2 * KVMAT)
#define SMEM_ATTN (128 * ASTRIDE + 2 * KVSTAGE + S_ * 4)

__device__ __forceinline__ void kv_prefetch(
    uint32_t sKV, int stg, int jb, int tid, int rowbase, int h,
    const __half* QKV)
{
    const uint32_t base = sKV + stg * KVSTAGE;
    const int r  = tid >> 2;
    const int c0 = tid & 3;
    const size_t go = (size_t)(rowbase + jb * 64 + r) * (3 * D_) + h * HD_;
    const __half* srcs[2] = { QKV + go + D_, QKV + go + 2 * D_ };
    #pragma unroll
    for (int m = 0; m < 2; m++) {
        const uint32_t mb = base + m * KVMAT + r * ASTRIDE;
        cp16(mb + c0 * 16,       srcs[m] + c0 * 8);
        cp16(mb + (c0 + 4) * 16, srcs[m] + (c0 + 4) * 8);
    }
}

__global__ void __launch_bounds__(256, 1) attn_mma_kernel(
    const __half* __restrict__ QKV, const void* __restrict__ mask,
    __half* __restrict__ Cc)
{
    const int it = blockIdx.x, h = blockIdx.y, b = blockIdx.z;
    extern __shared__ char sm8[];
    const uint32_t sb = smem_u32(sm8);
    const uint32_t sQ  = sb;
    const uint32_t sKV = sb + 128 * ASTRIDE;
    float* mk = (float*)(sm8 + 128 * ASTRIDE + 2 * KVSTAGE);

    const int tid = threadIdx.x, w = tid >> 5, lane = tid & 31;
    const int i0 = it * 128, rowbase = b * S_;
    const int frag_row = (lane & 7) + ((lane >> 3) & 1) * 8;
    const int frag_kb  = (lane >> 4) * 16;
    const float scale = 0.125f;

    {
        int r = tid >> 1;
        const size_t go = (size_t)(rowbase + i0 + r) * (3 * D_) + h * HD_;
        #pragma unroll
        for (int c = 0; c < 4; c++) {
            int ch = (tid & 1) * 4 + c;
            cp16(sQ + r * ASTRIDE + ch * 16, QKV + go + ch * 8);
        }
    }
    for (int i = tid; i < S_; i += 256)
        mk[i] = mask_val(mask, (b * H_ + h) * S_ + i);

    kv_prefetch(sKV, 0, 0, tid, rowbase, h, QKV);
    CP_COMMIT();
    CP_WAIT0();
    __syncthreads();

    uint32_t q[4][4];
    #pragma unroll
    for (int kk = 0; kk < 4; kk++) {
        uint32_t a = (w * 16 + frag_row) * ASTRIDE + kk * 32 + frag_kb;
        LDSM4(q[kk][0], q[kk][1], q[kk][2], q[kk][3], sQ + a);
    }

    float m_run[2] = { -3.0e38f, -3.0e38f };
    float l_run[2] = { 0.f, 0.f };
    float o[8][4];
    #pragma unroll
    for (int d = 0; d < 8; d++)
        #pragma unroll
        for (int r = 0; r < 4; r++) o[d][r] = 0.f;

    for (int jb = 0; jb < S_ / 64; jb++) {
        if (jb + 1 < S_ / 64) {
            kv_prefetch(sKV, (jb + 1) & 1, jb + 1, tid, rowbase, h, QKV);
            CP_COMMIT();
            CP_WAIT1();
        } else {
            CP_WAIT0();
        }
        __syncthreads();

        const uint32_t kvb = sKV + (jb & 1) * KVSTAGE;
        const uint32_t bK = kvb, bV = kvb + KVMAT;

        // ---- S = Q K^T ----
        float s[8][4];
        #pragma unroll
        for (int t = 0; t < 8; t++)
            #pragma unroll
            for (int r = 0; r < 4; r++) s[t][r] = 0.f;

        #pragma unroll
        for (int kk = 0; kk < 4; kk++) {
            #pragma unroll
            for (int nb = 0; nb < 4; nb++) {
                uint32_t k0, k1, k2, k3;
                uint32_t ad = (nb * 16 + frag_row) * ASTRIDE + kk * 32 + frag_kb;
                LDSM4(k0, k1, k2, k3, bK + ad);
                const int t0 = nb * 2, t1 = nb * 2 + 1;
                mma_f16(s[t0][0], s[t0][1], s[t0][2], s[t0][3],
                        q[kk][0], q[kk][1], q[kk][2], q[kk][3], k0, k2);
                mma_f16(s[t1][0], s[t1][1], s[t1][2], s[t1][3],
                        q[kk][0], q[kk][1], q[kk][2], q[kk][3], k1, k3);
            }
        }

        // ---- mask + scale ----
        #pragma unroll
        for (int t = 0; t < 8; t++) {
            float mv0 = mk[jb * 64 + t * 8 + (lane & 3) * 2];
            float mv1 = mk[jb * 64 + t * 8 + (lane & 3) * 2 + 1];
            s[t][0] = (mv0 > 0.5f) ? s[t][0] * scale : NEGV;
            s[t][1] = (mv1 > 0.5f) ? s[t][1] * scale : NEGV;
            s[t][2] = (mv0 > 0.5f) ? s[t][2] * scale : NEGV;
            s[t][3] = (mv1 > 0.5f) ? s[t][3] * scale : NEGV;
        }

        // ---- online softmax ----
        float mx0 = -3.0e38f, mx1 = -3.0e38f;
        #pragma unroll
        for (int t = 0; t < 8; t++) {
            mx0 = fmaxf(mx0, fmaxf(s[t][0], s[t][1]));
            mx1 = fmaxf(mx1, fmaxf(s[t][2], s[t][3]));
        }
        mx0 = fmaxf(mx0, __shfl_xor_sync(0xffffffffu, mx0, 1));
        mx0 = fmaxf(mx0, __shfl_xor_sync(0xffffffffu, mx0, 2));
        mx1 = fmaxf(mx1, __shfl_xor_sync(0xffffffffu, mx1, 1));
        mx1 = fmaxf(mx1, __shfl_xor_sync(0xffffffffu, mx1, 2));
        float nm0 = fmaxf(m_run[0], mx0), nm1 = fmaxf(m_run[1], mx1);
        float corr0 = __expf(m_run[0] - nm0), corr1 = __expf(m_run[1] - nm1);
        m_run[0] = nm0; m_run[1] = nm1;

        float sum0 = 0.f, sum1 = 0.f;
        #pragma unroll
        for (int t = 0; t < 8; t++) {
            s[t][0] = __expf(s[t][0] - nm0); sum0 += s[t][0];
            s[t][1] = __expf(s[t][1] - nm0); sum0 += s[t][1];
            s[t][2] = __expf(s[t][2] - nm1); sum1 += s[t][2];
            s[t][3] = __expf(s[t][3] - nm1); sum1 += s[t][3];
        }
        sum0 += __shfl_xor_sync(0xffffffffu, sum0, 1);
        sum0 += __shfl_xor_sync(0xffffffffu, sum0, 2);
        sum1 += __shfl_xor_sync(0xffffffffu, sum1, 1);
        sum1 += __shfl_xor_sync(0xffffffffu, sum1, 2);
        l_run[0] = l_run[0] * corr0 + sum0;
        l_run[1] = l_run[1] * corr1 + sum1;

        #pragma unroll
        for (int d = 0; d < 8; d++) {
            o[d][0] *= corr0; o[d][1] *= corr0;
            o[d][2] *= corr1; o[d][3] *= corr1;
        }

        // ---- O += P V ----
        #pragma unroll
        for (int kk = 0; kk < 4; kk++) {
            const int t0 = kk * 2, t1 = kk * 2 + 1;
            uint32_t pa[4];
            pa[0] = pack_h2(s[t0][0], s[t0][1]);
            pa[1] = pack_h2(s[t0][2], s[t0][3]);
            pa[2] = pack_h2(s[t1][0], s[t1][1]);
            pa[3] = pack_h2(s[t1][2], s[t1][3]);

            const uint32_t vrow =
                (kk * 16 + ((lane >> 3) & 1) * 8 + (lane & 7)) * ASTRIDE +
                (lane >> 4) * 16;
            #pragma unroll
            for (int qd = 0; qd < 4; qd++) {
                uint32_t v0, v1, v2, v3;
                LDSM4T(v0, v1, v2, v3, bV + vrow + qd * 32);
                const int d0 = qd * 2, d1 = qd * 2 + 1;
                mma_f16(o[d0][0], o[d0][1], o[d0][2], o[d0][3],
                        pa[0], pa[1], pa[2], pa[3], v0, v1);
                mma_f16(o[d1][0], o[d1][1], o[d1][2], o[d1][3],
                        pa[0], pa[1], pa[2], pa[3], v2, v3);
            }
        }
        __syncthreads();
    }

    const float inv0 = 1.f / l_run[0], inv1 = 1.f / l_run[1];
    const int tok0 = rowbase + i0 + w * 16 + (lane >> 2);
    #pragma unroll
    for (int d = 0; d < 8; d++) {
        int col = h * HD_ + d * 8 + (lane & 3) * 2;
        *(uint32_t*)(Cc + (size_t)tok0 * D_ + col) =
            pack_h2(o[d][0] * inv0, o[d][1] * inv0);
        *(uint32_t*)(Cc + (size_t)(tok0 + 8) * D_ + col) =
            pack_h2(o[d][2] * inv1, o[d][3] * inv1);
    }
}

// ---------------- residual + LayerNorm -------------------------------------
template<int SPLIT>
__global__ void __launch_bounds__(256) ln_residual_kernel(
    const float* __restrict__ a, const float* __restrict__ res,
    const float* __restrict__ gamma, const float* __restrict__ beta,
    float* __restrict__ out, __half* __restrict__ oh)
{
    const int row = blockIdx.x;
    const int tid = threadIdx.x;
    const float* pa = a   + (size_t)row * D_;
    const float* pr = res + (size_t)row * D_;

    float v[4], sum = 0.f, sq = 0.f;
    #pragma unroll
    for (int i = 0; i < 4; i++) {
        int c = tid + i * 256;
        float t = pa[c] + pr[c];
        v[i] = t; sum += t; sq += t * t;
    }
    #pragma unroll
    for (int o2 = 16; o2; o2 >>= 1) {
        sum += __shfl_xor_sync(0xffffffffu, sum, o2);
        sq  += __shfl_xor_sync(0xffffffffu, sq,  o2);
    }
    __shared__ float sh1[8], sh2[8];
    __shared__ float smean, srstd;
    if ((tid & 31) == 0) { sh1[tid >> 5] = sum; sh2[tid >> 5] = sq; }
    __syncthreads();
    if (tid == 0) {
        float s = 0.f, s2 = 0.f;
        #pragma unroll
        for (int i = 0; i < 8; i++) { s += sh1[i]; s2 += sh2[i]; }
        float mean = s * (1.f / D_);
        float var  = s2 * (1.f / D_) - mean * mean;
        smean = mean;
        srstd = rsqrtf(var + 1e-12f);
    }
    __syncthreads();
    float mean = smean, rstd = srstd;
    #pragma unroll
    for (int i = 0; i < 4; i++) {
        int c = tid + i * 256;
        float r = gamma[c] * (v[i] - mean) * rstd + beta[c];
        out[(size_t)row * D_ + c] = r;
        if (SPLIT) oh[(size_t)row * D_ + c] = __float2half_rn(r);
    }
}

// ---------------- launch ---------------------------------------------------
extern "C" void kernel_launch(void* const* d_in, const int* in_sizes, int n_in,
                              void* d_out, int out_size)
{
    const float* x    = (const float*)d_in[0];
    const void*  mask = d_in[1];
    const float* Wqkv = (const float*)d_in[2];
    const float* bqkv = (const float*)d_in[3];
    const float* Wo   = (const float*)d_in[4];
    const float* bo   = (const float*)d_in[5];
    const float* W1   = (const float*)d_in[6];
    const float* b1   = (const float*)d_in[7];
    const float* W2   = (const float*)d_in[8];
    const float* b2   = (const float*)d_in[9];
    const float* g1   = (const float*)d_in[10];
    const float* be1  = (const float*)d_in[11];
    const float* g2   = (const float*)d_in[12];
    const float* be2  = (const float*)d_in[13];
    float* out = (float*)d_out;

    float *attn, *hbuf, *f2;
    cudaGetSymbolAddress((void**)&attn, g_attn);
    cudaGetSymbolAddress((void**)&hbuf, g_h);
    cudaGetSymbolAddress((void**)&f2,   g_ffn2);

    __half *wq16, *wo16, *w116, *w216, *x16, *qkv16, *ctx16, *h16, *f116;
    cudaGetSymbolAddress((void**)&wq16, g_wqkv16);
    cudaGetSymbolAddress((void**)&wo16, g_wo16);
    cudaGetSymbolAddress((void**)&w116, g_w116);
    cudaGetSymbolAddress((void**)&w216, g_w216);
    cudaGetSymbolAddress((void**)&x16,  g_x16);
    cudaGetSymbolAddress((void**)&qkv16, g_qkv16);
    cudaGetSymbolAddress((void**)&ctx16, g_ctx16);
    cudaGetSymbolAddress((void**)&h16,  g_h16);
    cudaGetSymbolAddress((void**)&f116, g_f116);

    cudaFuncSetAttribute(attn_mma_kernel,
                         cudaFuncAttributeMaxDynamicSharedMemorySize, SMEM_ATTN);
    cudaFuncSetAttribute(gemm_mma<0,0>,
                         cudaFuncAttributeMaxDynamicSharedMemorySize, GEMM_SMEM);
    cudaFuncSetAttribute(gemm_mma<0,1>,
                         cudaFuncAttributeMaxDynamicSharedMemorySize, GEMM_SMEM);
    cudaFuncSetAttribute(gemm_mma<1,1>,
                         cudaFuncAttributeMaxDynamicSharedMemorySize, GEMM_SMEM);

    detect_mask_kernel<<<1, 256>>>((const unsigned char*)mask);

    cvt_h_kernel<<<(3*D_*D_/4 + 255)/256, 256>>>(Wqkv, wq16, 3*D_*D_);
    cvt_h_kernel<<<(D_*D_/4 + 255)/256, 256>>>(Wo, wo16, D_*D_);
    cvt_h_kernel<<<(FF_*D_/4 + 255)/256, 256>>>(W1, w116, FF_*D_);
    cvt_h_kernel<<<(D_*FF_/4 + 255)/256, 256>>>(W2, w216, D_*FF_);
    cvt_h_kernel<<<(NT*D_/4 + 255)/256, 256>>>(x, x16, NT*D_);

    // qkv = x @ Wqkv^T + bqkv -> fp16
    gemm_mma<0,1><<<dim3(3 * D_ / 128, NT / 128), 256, GEMM_SMEM>>>(
        x16, wq16, bqkv, nullptr, qkv16, NT, 3 * D_, D_);

    // attention -> ctx fp16
    attn_mma_kernel<<<dim3(S_ / 128, H_, B_), 256, SMEM_ATTN>>>(qkv16, mask, ctx16);

    // attn_out = ctx @ Wo^T + bo (fp32)
    gemm_mma<0,0><<<dim3(D_ / 128, NT / 128), 256, GEMM_SMEM>>>(
        ctx16, wo16, bo, attn, nullptr, NT, D_, D_);

    // h = LN1(attn_out + x) (fp32 + fp16)
    ln_residual_kernel<1><<<NT, 256>>>(attn, x, g1, be1, hbuf, h16);

    // f1 = relu(h @ W1^T + b1) -> fp16
    gemm_mma<1,1><<<dim3(FF_ / 128, NT / 128), 256, GEMM_SMEM>>>(
        h16, w116, b1, nullptr, f116, NT, FF_, D_);

    // f2 = f1 @ W2^T + b2 (fp32)
    gemm_mma<0,0><<<dim3(D_ / 128, NT / 128), 256, GEMM_SMEM>>>(
        f116, w216, b2, f2, nullptr, NT, D_, FF_);

    // out = LN2(f2 + h)
    ln_residual_kernel<0><<<NT, 256>>>(f2, hbuf, g2, be2, out, nullptr);
}